// round 7
// baseline (speedup 1.0000x reference)
#include <cuda_runtime.h>
#include <cuda_bf16.h>
#include <cstdint>

// ---------------- problem sizes ----------------
#define N_SRC0 200000
#define N_DST0 50000
#define N_DST1 10000
#define E0     800000
#define E1     160000
#define D      128

// ---------------- scratch (device globals; no allocs allowed) ----------------
__device__ float g_h0[(size_t)N_SRC0 * D];
__device__ float g_h1[(size_t)N_DST0 * D];
__device__ float g_hn0[(size_t)N_DST0 * D];
__device__ float g_hn1[(size_t)N_DST1 * D];
// transposed bf16 weight images Wt[n][k] = W[k][n], hi/lo split
__device__ __align__(16) __nv_bfloat16 g_WiH[16384], g_WiL[16384];
__device__ __align__(16) __nv_bfloat16 g_WsH[16384], g_WsL[16384];
__device__ __align__(16) __nv_bfloat16 g_WnH[16384], g_WnL[16384];
__device__ int g_deg0[N_DST0], g_rp0[N_DST0], g_cur0[N_DST0];
__device__ int g_deg1[N_DST1], g_rp1[N_DST1], g_cur1[N_DST1];
__device__ int g_es0[E0], g_es1[E1];
__device__ int g_incl[N_DST0];
__device__ int g_btot[64];

// ---------------- helpers ----------------
__device__ __forceinline__ uint32_t smem_to_u32(const void* p) {
    uint32_t a;
    asm("{ .reg .u64 t; cvta.to.shared.u64 t, %1; cvt.u32.u64 %0, t; }" : "=r"(a) : "l"(p));
    return a;
}

#define LDMATRIX_X4(r0, r1, r2, r3, addr) \
    asm volatile("ldmatrix.sync.aligned.m8n8.x4.shared.b16 {%0,%1,%2,%3}, [%4];" \
                 : "=r"(r0), "=r"(r1), "=r"(r2), "=r"(r3) : "r"(addr))

#define MMA_BF16(d, a, bv0, bv1) \
    asm volatile("mma.sync.aligned.m16n8k16.row.col.f32.bf16.bf16.f32 " \
                 "{%0,%1,%2,%3}, {%4,%5,%6,%7}, {%8,%9}, {%0,%1,%2,%3};" \
                 : "+f"((d)[0]), "+f"((d)[1]), "+f"((d)[2]), "+f"((d)[3]) \
                 : "r"((a)[0]), "r"((a)[1]), "r"((a)[2]), "r"((a)[3]), \
                   "r"(bv0), "r"(bv1))

#define CP_ASYNC16(dst, src) \
    asm volatile("cp.async.cg.shared.global [%0], [%1], 16;" :: "r"(dst), "l"(src))
#define CP_COMMIT() asm volatile("cp.async.commit_group;")
#define CP_WAIT0()  asm volatile("cp.async.wait_group 0;" ::: "memory")

// ---------------- weight image prep (one launch for all 3) ----------------
__global__ void wprep_kernel(const float* __restrict__ Wi, const float* __restrict__ Ws,
                             const float* __restrict__ Wn,
                             __nv_bfloat16* __restrict__ WiH, __nv_bfloat16* __restrict__ WiL,
                             __nv_bfloat16* __restrict__ WsH, __nv_bfloat16* __restrict__ WsL,
                             __nv_bfloat16* __restrict__ WnH, __nv_bfloat16* __restrict__ WnL) {
    int bid = blockIdx.x;
    const float* W = (bid < 64) ? Wi : (bid < 128) ? Ws : Wn;
    __nv_bfloat16* H = (bid < 64) ? WiH : (bid < 128) ? WsH : WnH;
    __nv_bfloat16* L = (bid < 64) ? WiL : (bid < 128) ? WsL : WnL;
    int idx = (bid & 63) * 256 + threadIdx.x;
    int n = idx >> 7, k = idx & 127;
    float w = W[k * 128 + n];
    __nv_bfloat16 h = __float2bfloat16(w);
    __nv_bfloat16 l = __float2bfloat16(w - __bfloat162float(h));
    H[idx] = h;
    L[idx] = l;
}

// ---------------- mma.sync GEMM: out = act(A@W + b [+ out_prev]) ----------------
#define SA 136
#define OFF_BIAS 0
#define OFF_AH   512
#define OFF_AL   (OFF_AH + 64 * SA * 2)
#define OFF_WH   (OFF_AL + 64 * SA * 2)
#define OFF_WL   (OFF_WH + 128 * SA * 2)
#define SMEM_TOTAL (OFF_WL + 128 * SA * 2)

template <bool RELU, bool ACCUM>
__global__ void __launch_bounds__(128)
gemm_mma(const float* __restrict__ A,
         const __nv_bfloat16* __restrict__ Wh, const __nv_bfloat16* __restrict__ Wl,
         const float* __restrict__ bias, float* __restrict__ out, int M)
{
    extern __shared__ char smem[];
    float* sbias = reinterpret_cast<float*>(smem + OFF_BIAS);
    const uint32_t sb = smem_to_u32(smem);
    const int tid = threadIdx.x;
    const int wid = tid >> 5;
    const int lane = tid & 31;
    const int warp_m = wid & 1;
    const int warp_n = wid >> 1;
    const int rowBase = blockIdx.x * 64;

    if (tid < 128) sbias[tid] = bias[tid];

    float acc[2][8][4];
#pragma unroll
    for (int i = 0; i < 2; i++)
#pragma unroll
        for (int j = 0; j < 8; j++)
#pragma unroll
            for (int r = 0; r < 4; r++) acc[i][j][r] = 0.f;

    const int tl = lane >> 3, trow = lane & 7;
    uint32_t aoff[2], boff[4];
#pragma unroll
    for (int mi = 0; mi < 2; mi++) {
        int row = warp_m * 32 + mi * 16 + trow + (tl & 1) * 8;
        int col = (tl >> 1) * 8;
        aoff[mi] = (uint32_t)(row * SA + col) * 2;
    }
#pragma unroll
    for (int nh = 0; nh < 4; nh++) {
        int n = warp_n * 64 + nh * 16 + (tl >> 1) * 8 + trow;
        int col = (tl & 1) * 8;
        boff[nh] = (uint32_t)(n * SA + col) * 2;
    }

    {
        const uint4* gh = reinterpret_cast<const uint4*>(Wh);
        const uint4* gl = reinterpret_cast<const uint4*>(Wl);
#pragma unroll
        for (int it = 0; it < 16; it++) {
            int idx = it * 128 + tid;
            int r = idx >> 4, wg = idx & 15;
            uint32_t d = (uint32_t)(r * SA + wg * 8) * 2;
            CP_ASYNC16(sb + OFF_WH + d, gh + idx);
            CP_ASYNC16(sb + OFF_WL + d, gl + idx);
        }
        CP_COMMIT();
    }
#pragma unroll
    for (int it = 0; it < 16; it++) {
        int e = it * 128 + tid;
        int row = e >> 5, c4 = e & 31;
        int grow = rowBase + row;
        float4 v = make_float4(0.f, 0.f, 0.f, 0.f);
        if (grow < M)
            v = *reinterpret_cast<const float4*>(A + (size_t)grow * D + c4 * 4);
        __nv_bfloat162 h01 = __float22bfloat162_rn(make_float2(v.x, v.y));
        __nv_bfloat162 h23 = __float22bfloat162_rn(make_float2(v.z, v.w));
        float2 f01 = __bfloat1622float2(h01);
        float2 f23 = __bfloat1622float2(h23);
        __nv_bfloat162 l01 = __float22bfloat162_rn(make_float2(v.x - f01.x, v.y - f01.y));
        __nv_bfloat162 l23 = __float22bfloat162_rn(make_float2(v.z - f23.x, v.w - f23.y));
        uint32_t d = (uint32_t)(row * SA + c4 * 4) * 2;
        uint2 hw, lw;
        hw.x = *reinterpret_cast<uint32_t*>(&h01);
        hw.y = *reinterpret_cast<uint32_t*>(&h23);
        lw.x = *reinterpret_cast<uint32_t*>(&l01);
        lw.y = *reinterpret_cast<uint32_t*>(&l23);
        *reinterpret_cast<uint2*>(smem + OFF_AH + d) = hw;
        *reinterpret_cast<uint2*>(smem + OFF_AL + d) = lw;
    }
    CP_WAIT0();
    __syncthreads();

#pragma unroll
    for (int ks = 0; ks < 8; ks++) {
        const uint32_t kb = ks * 32;
        uint32_t bh[16], bl[16];
#pragma unroll
        for (int nh = 0; nh < 4; nh++) {
            LDMATRIX_X4(bh[nh * 4], bh[nh * 4 + 1], bh[nh * 4 + 2], bh[nh * 4 + 3],
                        sb + OFF_WH + boff[nh] + kb);
            LDMATRIX_X4(bl[nh * 4], bl[nh * 4 + 1], bl[nh * 4 + 2], bl[nh * 4 + 3],
                        sb + OFF_WL + boff[nh] + kb);
        }
#pragma unroll
        for (int mi = 0; mi < 2; mi++) {
            uint32_t ah[4], al[4];
            LDMATRIX_X4(ah[0], ah[1], ah[2], ah[3], sb + OFF_AH + aoff[mi] + kb);
            LDMATRIX_X4(al[0], al[1], al[2], al[3], sb + OFF_AL + aoff[mi] + kb);
#pragma unroll
            for (int nj = 0; nj < 8; nj++) {
                int bi = (nj >> 1) * 4 + (nj & 1) * 2;
                MMA_BF16(acc[mi][nj], ah, bh[bi], bh[bi + 1]);
                MMA_BF16(acc[mi][nj], al, bh[bi], bh[bi + 1]);
                MMA_BF16(acc[mi][nj], ah, bl[bi], bl[bi + 1]);
            }
        }
    }

    const int g = lane >> 2, t = lane & 3;
#pragma unroll
    for (int mi = 0; mi < 2; mi++) {
        int row0 = rowBase + warp_m * 32 + mi * 16 + g;
        int row1 = row0 + 8;
#pragma unroll
        for (int nj = 0; nj < 8; nj++) {
            int col = warp_n * 64 + nj * 8 + t * 2;
            float bx = sbias[col], by = sbias[col + 1];
            if (row0 < M) {
                float2 v0 = make_float2(acc[mi][nj][0] + bx, acc[mi][nj][1] + by);
                float2* p0 = reinterpret_cast<float2*>(out + (size_t)row0 * D + col);
                if (ACCUM) { float2 q = *p0; v0.x += q.x; v0.y += q.y; }
                if (RELU) { v0.x = fmaxf(v0.x, 0.f); v0.y = fmaxf(v0.y, 0.f); }
                *p0 = v0;
            }
            if (row1 < M) {
                float2 v1 = make_float2(acc[mi][nj][2] + bx, acc[mi][nj][3] + by);
                float2* p1 = reinterpret_cast<float2*>(out + (size_t)row1 * D + col);
                if (ACCUM) { float2 q = *p1; v1.x += q.x; v1.y += q.y; }
                if (RELU) { v1.x = fmaxf(v1.x, 0.f); v1.y = fmaxf(v1.y, 0.f); }
                *p1 = v1;
            }
        }
    }
}

// ---------------- graph CSR build + mean aggregation ----------------
__global__ void hist_kernel(const int* __restrict__ dst, int* __restrict__ deg, int E) {
    int e = blockIdx.x * blockDim.x + threadIdx.x;
    if (e < E) atomicAdd(&deg[dst[e]], 1);
}

__global__ void scan_pass1(const int* __restrict__ deg, int* __restrict__ incl,
                           int* __restrict__ btot, int n) {
    __shared__ int wsum[32];
    int t = threadIdx.x;
    int i = blockIdx.x * 1024 + t;
    int v = (i < n) ? deg[i] : 0;
    int x = v;
#pragma unroll
    for (int o = 1; o < 32; o <<= 1) {
        int y = __shfl_up_sync(0xffffffffu, x, o);
        if ((t & 31) >= o) x += y;
    }
    if ((t & 31) == 31) wsum[t >> 5] = x;
    __syncthreads();
    if (t < 32) {
        int s = wsum[t];
#pragma unroll
        for (int o = 1; o < 32; o <<= 1) {
            int y = __shfl_up_sync(0xffffffffu, s, o);
            if (t >= o) s += y;
        }
        wsum[t] = s;
    }
    __syncthreads();
    int base = (t >= 32) ? wsum[(t >> 5) - 1] : 0;
    int inc = x + base;
    if (i < n) incl[i] = inc;
    if (t == 1023) btot[blockIdx.x] = inc;
}

__global__ void scan_pass2(int* __restrict__ btot, int nb) {
    __shared__ int s[64];
    int t = threadIdx.x;
    s[t] = (t < nb) ? btot[t] : 0;
    __syncthreads();
#pragma unroll
    for (int o = 1; o < 64; o <<= 1) {
        int v = (t >= o) ? s[t - o] : 0;
        __syncthreads();
        s[t] += v;
        __syncthreads();
    }
    if (t < nb) btot[t] = t ? s[t - 1] : 0;
}

__global__ void scan_pass3(const int* __restrict__ incl, const int* __restrict__ deg,
                           const int* __restrict__ btot, int* __restrict__ rp,
                           int* __restrict__ cur, int n) {
    int i = blockIdx.x * 1024 + threadIdx.x;
    if (i < n) {
        int r = btot[blockIdx.x] + incl[i] - deg[i];
        rp[i] = r;
        cur[i] = r;
    }
}

__global__ void fill_kernel(const int* __restrict__ src, const int* __restrict__ dst,
                            int* __restrict__ cur, int* __restrict__ es, int E) {
    int e = blockIdx.x * blockDim.x + threadIdx.x;
    if (e < E) {
        int p = atomicAdd(&cur[dst[e]], 1);
        es[p] = src[e];
    }
}

// one warp per dst node; 8-wide unrolled gather (8 in-flight loads)
__global__ void agg_kernel(const float* __restrict__ h, const int* __restrict__ rp,
                           const int* __restrict__ deg, const int* __restrict__ es,
                           float* __restrict__ hn, int ndst) {
    int lane = threadIdx.x & 31;
    int w = (blockIdx.x * blockDim.x + threadIdx.x) >> 5;
    if (w >= ndst) return;
    int start = rp[w];
    int cnt = deg[w];
    float4 a0 = make_float4(0.f, 0.f, 0.f, 0.f);
    float4 a1 = make_float4(0.f, 0.f, 0.f, 0.f);
    float4 a2 = make_float4(0.f, 0.f, 0.f, 0.f);
    float4 a3 = make_float4(0.f, 0.f, 0.f, 0.f);
    const float4* h4 = reinterpret_cast<const float4*>(h);
    for (int base = 0; base < cnt; base += 32) {
        int n = min(32, cnt - base);
        int sidx = (lane < n) ? es[start + base + lane] : 0;
        int j = 0;
        for (; j + 8 <= n; j += 8) {
            int s0 = __shfl_sync(0xffffffffu, sidx, j);
            int s1 = __shfl_sync(0xffffffffu, sidx, j + 1);
            int s2 = __shfl_sync(0xffffffffu, sidx, j + 2);
            int s3 = __shfl_sync(0xffffffffu, sidx, j + 3);
            int s4 = __shfl_sync(0xffffffffu, sidx, j + 4);
            int s5 = __shfl_sync(0xffffffffu, sidx, j + 5);
            int s6 = __shfl_sync(0xffffffffu, sidx, j + 6);
            int s7 = __shfl_sync(0xffffffffu, sidx, j + 7);
            float4 v0 = h4[(size_t)s0 * 32 + lane];
            float4 v1 = h4[(size_t)s1 * 32 + lane];
            float4 v2 = h4[(size_t)s2 * 32 + lane];
            float4 v3 = h4[(size_t)s3 * 32 + lane];
            float4 v4 = h4[(size_t)s4 * 32 + lane];
            float4 v5 = h4[(size_t)s5 * 32 + lane];
            float4 v6 = h4[(size_t)s6 * 32 + lane];
            float4 v7 = h4[(size_t)s7 * 32 + lane];
            a0.x += v0.x; a0.y += v0.y; a0.z += v0.z; a0.w += v0.w;
            a1.x += v1.x; a1.y += v1.y; a1.z += v1.z; a1.w += v1.w;
            a2.x += v2.x; a2.y += v2.y; a2.z += v2.z; a2.w += v2.w;
            a3.x += v3.x; a3.y += v3.y; a3.z += v3.z; a3.w += v3.w;
            a0.x += v4.x; a0.y += v4.y; a0.z += v4.z; a0.w += v4.w;
            a1.x += v5.x; a1.y += v5.y; a1.z += v5.z; a1.w += v5.w;
            a2.x += v6.x; a2.y += v6.y; a2.z += v6.z; a2.w += v6.w;
            a3.x += v7.x; a3.y += v7.y; a3.z += v7.z; a3.w += v7.w;
        }
        for (; j < n; j++) {
            int s0 = __shfl_sync(0xffffffffu, sidx, j);
            float4 v0 = h4[(size_t)s0 * 32 + lane];
            a0.x += v0.x; a0.y += v0.y; a0.z += v0.z; a0.w += v0.w;
        }
    }
    float inv = 1.0f / (float)max(cnt, 1);
    reinterpret_cast<float4*>(hn)[(size_t)w * 32 + lane] =
        make_float4((a0.x + a1.x + a2.x + a3.x) * inv, (a0.y + a1.y + a2.y + a3.y) * inv,
                    (a0.z + a1.z + a2.z + a3.z) * inv, (a0.w + a1.w + a2.w + a3.w) * inv);
}

// ---------------- launch ----------------
extern "C" void kernel_launch(void* const* d_in, const int* in_sizes, int n_in,
                              void* d_out, int out_size) {
    const float* feat    = (const float*)d_in[0];
    const int*   src0    = (const int*)d_in[1];
    const int*   dst0    = (const int*)d_in[2];
    const int*   src1    = (const int*)d_in[3];
    const int*   dst1    = (const int*)d_in[4];
    const float* W_init  = (const float*)d_in[5];
    const float* b_init  = (const float*)d_in[6];
    const float* W_self  = (const float*)d_in[7];
    const float* b_self  = (const float*)d_in[8];
    const float* W_neigh = (const float*)d_in[9];
    const float* b_neigh = (const float*)d_in[10];
    float* out = (float*)d_out;

    float *h0, *h1, *hn0, *hn1;
    __nv_bfloat16 *WiH, *WiL, *WsH, *WsL, *WnH, *WnL;
    int *deg0, *rp0, *cur0, *es0, *deg1, *rp1, *cur1, *es1, *incl, *btot;
    cudaGetSymbolAddress((void**)&h0,  g_h0);
    cudaGetSymbolAddress((void**)&h1,  g_h1);
    cudaGetSymbolAddress((void**)&hn0, g_hn0);
    cudaGetSymbolAddress((void**)&hn1, g_hn1);
    cudaGetSymbolAddress((void**)&WiH, g_WiH);
    cudaGetSymbolAddress((void**)&WiL, g_WiL);
    cudaGetSymbolAddress((void**)&WsH, g_WsH);
    cudaGetSymbolAddress((void**)&WsL, g_WsL);
    cudaGetSymbolAddress((void**)&WnH, g_WnH);
    cudaGetSymbolAddress((void**)&WnL, g_WnL);
    cudaGetSymbolAddress((void**)&deg0, g_deg0);
    cudaGetSymbolAddress((void**)&rp0,  g_rp0);
    cudaGetSymbolAddress((void**)&cur0, g_cur0);
    cudaGetSymbolAddress((void**)&es0,  g_es0);
    cudaGetSymbolAddress((void**)&deg1, g_deg1);
    cudaGetSymbolAddress((void**)&rp1,  g_rp1);
    cudaGetSymbolAddress((void**)&cur1, g_cur1);
    cudaGetSymbolAddress((void**)&es1,  g_es1);
    cudaGetSymbolAddress((void**)&incl, g_incl);
    cudaGetSymbolAddress((void**)&btot, g_btot);

    cudaFuncSetAttribute(gemm_mma<true, false>,
                         cudaFuncAttributeMaxDynamicSharedMemorySize, SMEM_TOTAL);
    cudaFuncSetAttribute(gemm_mma<false, false>,
                         cudaFuncAttributeMaxDynamicSharedMemorySize, SMEM_TOTAL);
    cudaFuncSetAttribute(gemm_mma<true, true>,
                         cudaFuncAttributeMaxDynamicSharedMemorySize, SMEM_TOTAL);
    cudaFuncSetAttribute(gemm_mma<false, true>,
                         cudaFuncAttributeMaxDynamicSharedMemorySize, SMEM_TOTAL);

    // side stream + events (created once on the first, non-captured call)
    static cudaStream_t sA = nullptr;
    static cudaEvent_t evFork = nullptr, ev0 = nullptr, ev1 = nullptr;
    static cudaEvent_t evG1 = nullptr, evG2 = nullptr, evS2 = nullptr, evS3 = nullptr;
    if (!sA) {
        cudaStreamCreateWithFlags(&sA, cudaStreamNonBlocking);
        cudaEventCreateWithFlags(&evFork, cudaEventDisableTiming);
        cudaEventCreateWithFlags(&ev0, cudaEventDisableTiming);
        cudaEventCreateWithFlags(&ev1, cudaEventDisableTiming);
        cudaEventCreateWithFlags(&evG1, cudaEventDisableTiming);
        cudaEventCreateWithFlags(&evG2, cudaEventDisableTiming);
        cudaEventCreateWithFlags(&evS2, cudaEventDisableTiming);
        cudaEventCreateWithFlags(&evS3, cudaEventDisableTiming);
    }

    const int NB0 = (N_DST0 + 1023) / 1024;   // 49
    const int NB1 = (N_DST1 + 1023) / 1024;   // 10

    // ---- fork side stream ----
    cudaEventRecord(evFork, 0);
    cudaStreamWaitEvent(sA, evFork, 0);

    // side stream: CSR builds (layer 0 then layer 1; shared temps serialize)
    cudaMemsetAsync(deg0, 0, N_DST0 * sizeof(int), sA);
    hist_kernel<<<(E0 + 255) / 256, 256, 0, sA>>>(dst0, deg0, E0);
    scan_pass1<<<NB0, 1024, 0, sA>>>(deg0, incl, btot, N_DST0);
    scan_pass2<<<1, 64, 0, sA>>>(btot, NB0);
    scan_pass3<<<NB0, 1024, 0, sA>>>(incl, deg0, btot, rp0, cur0, N_DST0);
    fill_kernel<<<(E0 + 255) / 256, 256, 0, sA>>>(src0, dst0, cur0, es0, E0);
    cudaEventRecord(ev0, sA);
    cudaMemsetAsync(deg1, 0, N_DST1 * sizeof(int), sA);
    hist_kernel<<<(E1 + 255) / 256, 256, 0, sA>>>(dst1, deg1, E1);
    scan_pass1<<<NB1, 1024, 0, sA>>>(deg1, incl, btot, N_DST1);
    scan_pass2<<<1, 64, 0, sA>>>(btot, NB1);
    scan_pass3<<<NB1, 1024, 0, sA>>>(incl, deg1, btot, rp1, cur1, N_DST1);
    fill_kernel<<<(E1 + 255) / 256, 256, 0, sA>>>(src1, dst1, cur1, es1, E1);
    cudaEventRecord(ev1, sA);

    // main: weight prep + fc_init GEMM  h0 = relu(feat@Wi + bi)
    wprep_kernel<<<192, 256>>>(W_init, W_self, W_neigh, WiH, WiL, WsH, WsL, WnH, WnL);
    gemm_mma<true, false><<<(N_SRC0 + 63) / 64, 128, SMEM_TOTAL>>>(
        feat, WiH, WiL, b_init, h0, N_SRC0);
    cudaEventRecord(evG1, 0);

    // side: layer-0 self GEMM (h1 = h0@Ws + b_self), overlaps agg0 on main
    cudaStreamWaitEvent(sA, evG1, 0);
    gemm_mma<false, false><<<(N_DST0 + 63) / 64, 128, SMEM_TOTAL, sA>>>(
        h0, WsH, WsL, b_self, h1, N_DST0);
    cudaEventRecord(evS2, sA);

    // main: join CSR0, aggregate layer 0
    cudaStreamWaitEvent(0, ev0, 0);
    agg_kernel<<<N_DST0 / 8, 256>>>(h0, rp0, deg0, es0, hn0, N_DST0);

    // main: layer-0 neighbor GEMM  h1 = relu(h1 + hn0@Wn + b_neigh)
    cudaStreamWaitEvent(0, evS2, 0);
    gemm_mma<true, true><<<(N_DST0 + 63) / 64, 128, SMEM_TOTAL>>>(
        hn0, WnH, WnL, b_neigh, h1, N_DST0);
    cudaEventRecord(evG2, 0);

    // side: layer-1 self GEMM (out = h1@Ws + b_self), overlaps agg1 on main
    cudaStreamWaitEvent(sA, evG2, 0);
    gemm_mma<false, false><<<(N_DST1 + 63) / 64, 128, SMEM_TOTAL, sA>>>(
        h1, WsH, WsL, b_self, out, N_DST1);
    cudaEventRecord(evS3, sA);

    // main: join CSR1, aggregate layer 1
    cudaStreamWaitEvent(0, ev1, 0);
    agg_kernel<<<N_DST1 / 8, 256>>>(h1, rp1, deg1, es1, hn1, N_DST1);

    // main: layer-1 neighbor GEMM  out = out + hn1@Wn + b_neigh (no relu)
    cudaStreamWaitEvent(0, evS3, 0);
    gemm_mma<false, true><<<(N_DST1 + 63) / 64, 128, SMEM_TOTAL>>>(
        hn1, WnH, WnL, b_neigh, out, N_DST1);
}

// round 9
// speedup vs baseline: 1.0548x; 1.0548x over previous
#include <cuda_runtime.h>
#include <cuda_bf16.h>
#include <cstdint>

// ---------------- problem sizes ----------------
#define N_SRC0 200000
#define N_DST0 50000
#define N_DST1 10000
#define E0     800000
#define E1     160000
#define D      128

// ---------------- scratch (device globals; no allocs allowed) ----------------
__device__ float g_h0[(size_t)N_SRC0 * D];
__device__ __nv_bfloat16 g_h0b[(size_t)N_SRC0 * D];   // bf16 copy for gather
__device__ float g_h1[(size_t)N_DST0 * D];
__device__ float g_hn0[(size_t)N_DST0 * D];
__device__ float g_hn1[(size_t)N_DST1 * D];
// transposed bf16 weight images Wt[n][k] = W[k][n], hi/lo split
__device__ __align__(16) __nv_bfloat16 g_WiH[16384], g_WiL[16384];
__device__ __align__(16) __nv_bfloat16 g_WsH[16384], g_WsL[16384];
__device__ __align__(16) __nv_bfloat16 g_WnH[16384], g_WnL[16384];
__device__ int g_deg0[N_DST0], g_rp0[N_DST0], g_cur0[N_DST0];
__device__ int g_deg1[N_DST1], g_rp1[N_DST1], g_cur1[N_DST1];
__device__ int g_es0[E0], g_es1[E1];
__device__ int g_incl[N_DST0];
__device__ int g_btot[64];

// ---------------- helpers ----------------
__device__ __forceinline__ uint32_t smem_to_u32(const void* p) {
    uint32_t a;
    asm("{ .reg .u64 t; cvta.to.shared.u64 t, %1; cvt.u32.u64 %0, t; }" : "=r"(a) : "l"(p));
    return a;
}

#define LDMATRIX_X4(r0, r1, r2, r3, addr) \
    asm volatile("ldmatrix.sync.aligned.m8n8.x4.shared.b16 {%0,%1,%2,%3}, [%4];" \
                 : "=r"(r0), "=r"(r1), "=r"(r2), "=r"(r3) : "r"(addr))

#define MMA_BF16(d, a, bv0, bv1) \
    asm volatile("mma.sync.aligned.m16n8k16.row.col.f32.bf16.bf16.f32 " \
                 "{%0,%1,%2,%3}, {%4,%5,%6,%7}, {%8,%9}, {%0,%1,%2,%3};" \
                 : "+f"((d)[0]), "+f"((d)[1]), "+f"((d)[2]), "+f"((d)[3]) \
                 : "r"((a)[0]), "r"((a)[1]), "r"((a)[2]), "r"((a)[3]), \
                   "r"(bv0), "r"(bv1))

#define CP_ASYNC16(dst, src) \
    asm volatile("cp.async.cg.shared.global [%0], [%1], 16;" :: "r"(dst), "l"(src))
#define CP_COMMIT() asm volatile("cp.async.commit_group;")
#define CP_WAIT0()  asm volatile("cp.async.wait_group 0;" ::: "memory")

// ---------------- weight image prep (one launch for all 3) ----------------
__global__ void wprep_kernel(const float* __restrict__ Wi, const float* __restrict__ Ws,
                             const float* __restrict__ Wn,
                             __nv_bfloat16* __restrict__ WiH, __nv_bfloat16* __restrict__ WiL,
                             __nv_bfloat16* __restrict__ WsH, __nv_bfloat16* __restrict__ WsL,
                             __nv_bfloat16* __restrict__ WnH, __nv_bfloat16* __restrict__ WnL) {
    int bid = blockIdx.x;
    const float* W = (bid < 64) ? Wi : (bid < 128) ? Ws : Wn;
    __nv_bfloat16* H = (bid < 64) ? WiH : (bid < 128) ? WsH : WnH;
    __nv_bfloat16* L = (bid < 64) ? WiL : (bid < 128) ? WsL : WnL;
    int idx = (bid & 63) * 256 + threadIdx.x;
    int n = idx >> 7, k = idx & 127;
    float w = W[k * 128 + n];
    __nv_bfloat16 h = __float2bfloat16(w);
    __nv_bfloat16 l = __float2bfloat16(w - __bfloat162float(h));
    H[idx] = h;
    L[idx] = l;
}

// ---------------- mma.sync GEMM: out = act(A0@W0 [+ A1@W1] + b0 [+ b1]) ----------------
#define SA 136
#define OFF_BIAS 0
#define OFF_AH   512
#define OFF_AL   (OFF_AH + 64 * SA * 2)
#define OFF_WH   (OFF_AL + 64 * SA * 2)
#define OFF_WL   (OFF_WH + 128 * SA * 2)
#define SMEM_TOTAL (OFF_WL + 128 * SA * 2)

template <bool RELU, bool DUAL, bool WBF16>
__global__ void __launch_bounds__(128)
gemm_mma(const float* __restrict__ A0, const float* __restrict__ A1,
         const __nv_bfloat16* __restrict__ W0h, const __nv_bfloat16* __restrict__ W0l,
         const __nv_bfloat16* __restrict__ W1h, const __nv_bfloat16* __restrict__ W1l,
         const float* __restrict__ b0, const float* __restrict__ b1,
         float* __restrict__ out, __nv_bfloat16* __restrict__ outb, int M)
{
    extern __shared__ char smem[];
    float* sbias = reinterpret_cast<float*>(smem + OFF_BIAS);
    const uint32_t sb = smem_to_u32(smem);
    const int tid = threadIdx.x;
    const int wid = tid >> 5;
    const int lane = tid & 31;
    const int warp_m = wid & 1;
    const int warp_n = wid >> 1;
    const int rowBase = blockIdx.x * 64;

    if (tid < 128) {
        float b = b0[tid];
        if (DUAL) b += b1[tid];
        sbias[tid] = b;
    }

    float acc[2][8][4];
#pragma unroll
    for (int i = 0; i < 2; i++)
#pragma unroll
        for (int j = 0; j < 8; j++)
#pragma unroll
            for (int r = 0; r < 4; r++) acc[i][j][r] = 0.f;

    const int tl = lane >> 3, trow = lane & 7;
    uint32_t aoff[2], boff[4];
#pragma unroll
    for (int mi = 0; mi < 2; mi++) {
        int row = warp_m * 32 + mi * 16 + trow + (tl & 1) * 8;
        int col = (tl >> 1) * 8;
        aoff[mi] = (uint32_t)(row * SA + col) * 2;
    }
#pragma unroll
    for (int nh = 0; nh < 4; nh++) {
        int n = warp_n * 64 + nh * 16 + (tl >> 1) * 8 + trow;
        int col = (tl & 1) * 8;
        boff[nh] = (uint32_t)(n * SA + col) * 2;
    }

    const int npass = DUAL ? 2 : 1;
#pragma unroll 1
    for (int pass = 0; pass < npass; ++pass) {
        const float* A = pass ? A1 : A0;
        const __nv_bfloat16* Wh = pass ? W1h : W0h;
        const __nv_bfloat16* Wl = pass ? W1l : W0l;

        {
            const uint4* gh = reinterpret_cast<const uint4*>(Wh);
            const uint4* gl = reinterpret_cast<const uint4*>(Wl);
#pragma unroll
            for (int it = 0; it < 16; it++) {
                int idx = it * 128 + tid;
                int r = idx >> 4, wg = idx & 15;
                uint32_t d = (uint32_t)(r * SA + wg * 8) * 2;
                CP_ASYNC16(sb + OFF_WH + d, gh + idx);
                CP_ASYNC16(sb + OFF_WL + d, gl + idx);
            }
            CP_COMMIT();
        }
#pragma unroll
        for (int it = 0; it < 16; it++) {
            int e = it * 128 + tid;
            int row = e >> 5, c4 = e & 31;
            int grow = rowBase + row;
            float4 v = make_float4(0.f, 0.f, 0.f, 0.f);
            if (grow < M)
                v = *reinterpret_cast<const float4*>(A + (size_t)grow * D + c4 * 4);
            __nv_bfloat162 h01 = __float22bfloat162_rn(make_float2(v.x, v.y));
            __nv_bfloat162 h23 = __float22bfloat162_rn(make_float2(v.z, v.w));
            float2 f01 = __bfloat1622float2(h01);
            float2 f23 = __bfloat1622float2(h23);
            __nv_bfloat162 l01 = __float22bfloat162_rn(make_float2(v.x - f01.x, v.y - f01.y));
            __nv_bfloat162 l23 = __float22bfloat162_rn(make_float2(v.z - f23.x, v.w - f23.y));
            uint32_t d = (uint32_t)(row * SA + c4 * 4) * 2;
            uint2 hw, lw;
            hw.x = *reinterpret_cast<uint32_t*>(&h01);
            hw.y = *reinterpret_cast<uint32_t*>(&h23);
            lw.x = *reinterpret_cast<uint32_t*>(&l01);
            lw.y = *reinterpret_cast<uint32_t*>(&l23);
            *reinterpret_cast<uint2*>(smem + OFF_AH + d) = hw;
            *reinterpret_cast<uint2*>(smem + OFF_AL + d) = lw;
        }
        CP_WAIT0();
        __syncthreads();

#pragma unroll
        for (int ks = 0; ks < 8; ks++) {
            const uint32_t kb = ks * 32;
            uint32_t bh[16], bl[16];
#pragma unroll
            for (int nh = 0; nh < 4; nh++) {
                LDMATRIX_X4(bh[nh * 4], bh[nh * 4 + 1], bh[nh * 4 + 2], bh[nh * 4 + 3],
                            sb + OFF_WH + boff[nh] + kb);
                LDMATRIX_X4(bl[nh * 4], bl[nh * 4 + 1], bl[nh * 4 + 2], bl[nh * 4 + 3],
                            sb + OFF_WL + boff[nh] + kb);
            }
#pragma unroll
            for (int mi = 0; mi < 2; mi++) {
                uint32_t ah[4], al[4];
                LDMATRIX_X4(ah[0], ah[1], ah[2], ah[3], sb + OFF_AH + aoff[mi] + kb);
                LDMATRIX_X4(al[0], al[1], al[2], al[3], sb + OFF_AL + aoff[mi] + kb);
#pragma unroll
                for (int nj = 0; nj < 8; nj++) {
                    int bi = (nj >> 1) * 4 + (nj & 1) * 2;
                    MMA_BF16(acc[mi][nj], ah, bh[bi], bh[bi + 1]);
                    MMA_BF16(acc[mi][nj], al, bh[bi], bh[bi + 1]);
                    MMA_BF16(acc[mi][nj], ah, bl[bi], bl[bi + 1]);
                }
            }
        }
        __syncthreads();
    }

    const int g = lane >> 2, t = lane & 3;
#pragma unroll
    for (int mi = 0; mi < 2; mi++) {
        int row0 = rowBase + warp_m * 32 + mi * 16 + g;
        int row1 = row0 + 8;
#pragma unroll
        for (int nj = 0; nj < 8; nj++) {
            int col = warp_n * 64 + nj * 8 + t * 2;
            float bx = sbias[col], by = sbias[col + 1];
            float2 v0 = make_float2(acc[mi][nj][0] + bx, acc[mi][nj][1] + by);
            float2 v1 = make_float2(acc[mi][nj][2] + bx, acc[mi][nj][3] + by);
            if (RELU) {
                v0.x = fmaxf(v0.x, 0.f); v0.y = fmaxf(v0.y, 0.f);
                v1.x = fmaxf(v1.x, 0.f); v1.y = fmaxf(v1.y, 0.f);
            }
            if (row0 < M) {
                *reinterpret_cast<float2*>(out + (size_t)row0 * D + col) = v0;
                if (WBF16) {
                    __nv_bfloat162 b2 = __float22bfloat162_rn(v0);
                    *reinterpret_cast<__nv_bfloat162*>(outb + (size_t)row0 * D + col) = b2;
                }
            }
            if (row1 < M) {
                *reinterpret_cast<float2*>(out + (size_t)row1 * D + col) = v1;
                if (WBF16) {
                    __nv_bfloat162 b2 = __float22bfloat162_rn(v1);
                    *reinterpret_cast<__nv_bfloat162*>(outb + (size_t)row1 * D + col) = b2;
                }
            }
        }
    }
}

// ---------------- graph CSR build + mean aggregation ----------------
__global__ void hist_kernel(const int* __restrict__ dst, int* __restrict__ deg, int E) {
    int e = blockIdx.x * blockDim.x + threadIdx.x;
    if (e < E) atomicAdd(&deg[dst[e]], 1);
}

__global__ void scan_pass1(const int* __restrict__ deg, int* __restrict__ incl,
                           int* __restrict__ btot, int n) {
    __shared__ int wsum[32];
    int t = threadIdx.x;
    int i = blockIdx.x * 1024 + t;
    int v = (i < n) ? deg[i] : 0;
    int x = v;
#pragma unroll
    for (int o = 1; o < 32; o <<= 1) {
        int y = __shfl_up_sync(0xffffffffu, x, o);
        if ((t & 31) >= o) x += y;
    }
    if ((t & 31) == 31) wsum[t >> 5] = x;
    __syncthreads();
    if (t < 32) {
        int s = wsum[t];
#pragma unroll
        for (int o = 1; o < 32; o <<= 1) {
            int y = __shfl_up_sync(0xffffffffu, s, o);
            if (t >= o) s += y;
        }
        wsum[t] = s;
    }
    __syncthreads();
    int base = (t >= 32) ? wsum[(t >> 5) - 1] : 0;
    int inc = x + base;
    if (i < n) incl[i] = inc;
    if (t == 1023) btot[blockIdx.x] = inc;
}

__global__ void scan_pass2(int* __restrict__ btot, int nb) {
    __shared__ int s[64];
    int t = threadIdx.x;
    s[t] = (t < nb) ? btot[t] : 0;
    __syncthreads();
#pragma unroll
    for (int o = 1; o < 64; o <<= 1) {
        int v = (t >= o) ? s[t - o] : 0;
        __syncthreads();
        s[t] += v;
        __syncthreads();
    }
    if (t < nb) btot[t] = t ? s[t - 1] : 0;
}

__global__ void scan_pass3(const int* __restrict__ incl, const int* __restrict__ deg,
                           const int* __restrict__ btot, int* __restrict__ rp,
                           int* __restrict__ cur, int n) {
    int i = blockIdx.x * 1024 + threadIdx.x;
    if (i < n) {
        int r = btot[blockIdx.x] + incl[i] - deg[i];
        rp[i] = r;
        cur[i] = r;
    }
}

__global__ void fill_kernel(const int* __restrict__ src, const int* __restrict__ dst,
                            int* __restrict__ cur, int* __restrict__ es, int E) {
    int e = blockIdx.x * blockDim.x + threadIdx.x;
    if (e < E) {
        int p = atomicAdd(&cur[dst[e]], 1);
        es[p] = src[e];
    }
}

// fp32 gather aggregation (layer 1); 8-wide unroll
__global__ void agg_kernel(const float* __restrict__ h, const int* __restrict__ rp,
                           const int* __restrict__ deg, const int* __restrict__ es,
                           float* __restrict__ hn, int ndst) {
    int lane = threadIdx.x & 31;
    int w = (blockIdx.x * blockDim.x + threadIdx.x) >> 5;
    if (w >= ndst) return;
    int start = rp[w];
    int cnt = deg[w];
    float4 a0 = make_float4(0.f, 0.f, 0.f, 0.f);
    float4 a1 = make_float4(0.f, 0.f, 0.f, 0.f);
    float4 a2 = make_float4(0.f, 0.f, 0.f, 0.f);
    float4 a3 = make_float4(0.f, 0.f, 0.f, 0.f);
    const float4* h4 = reinterpret_cast<const float4*>(h);
    for (int base = 0; base < cnt; base += 32) {
        int n = min(32, cnt - base);
        int sidx = (lane < n) ? es[start + base + lane] : 0;
        int j = 0;
        for (; j + 8 <= n; j += 8) {
            int s0 = __shfl_sync(0xffffffffu, sidx, j);
            int s1 = __shfl_sync(0xffffffffu, sidx, j + 1);
            int s2 = __shfl_sync(0xffffffffu, sidx, j + 2);
            int s3 = __shfl_sync(0xffffffffu, sidx, j + 3);
            int s4 = __shfl_sync(0xffffffffu, sidx, j + 4);
            int s5 = __shfl_sync(0xffffffffu, sidx, j + 5);
            int s6 = __shfl_sync(0xffffffffu, sidx, j + 6);
            int s7 = __shfl_sync(0xffffffffu, sidx, j + 7);
            float4 v0 = h4[(size_t)s0 * 32 + lane];
            float4 v1 = h4[(size_t)s1 * 32 + lane];
            float4 v2 = h4[(size_t)s2 * 32 + lane];
            float4 v3 = h4[(size_t)s3 * 32 + lane];
            float4 v4 = h4[(size_t)s4 * 32 + lane];
            float4 v5 = h4[(size_t)s5 * 32 + lane];
            float4 v6 = h4[(size_t)s6 * 32 + lane];
            float4 v7 = h4[(size_t)s7 * 32 + lane];
            a0.x += v0.x; a0.y += v0.y; a0.z += v0.z; a0.w += v0.w;
            a1.x += v1.x; a1.y += v1.y; a1.z += v1.z; a1.w += v1.w;
            a2.x += v2.x; a2.y += v2.y; a2.z += v2.z; a2.w += v2.w;
            a3.x += v3.x; a3.y += v3.y; a3.z += v3.z; a3.w += v3.w;
            a0.x += v4.x; a0.y += v4.y; a0.z += v4.z; a0.w += v4.w;
            a1.x += v5.x; a1.y += v5.y; a1.z += v5.z; a1.w += v5.w;
            a2.x += v6.x; a2.y += v6.y; a2.z += v6.z; a2.w += v6.w;
            a3.x += v7.x; a3.y += v7.y; a3.z += v7.z; a3.w += v7.w;
        }
        for (; j < n; j++) {
            int s0 = __shfl_sync(0xffffffffu, sidx, j);
            float4 v0 = h4[(size_t)s0 * 32 + lane];
            a0.x += v0.x; a0.y += v0.y; a0.z += v0.z; a0.w += v0.w;
        }
    }
    float inv = 1.0f / (float)max(cnt, 1);
    reinterpret_cast<float4*>(hn)[(size_t)w * 32 + lane] =
        make_float4((a0.x + a1.x + a2.x + a3.x) * inv, (a0.y + a1.y + a2.y + a3.y) * inv,
                    (a0.z + a1.z + a2.z + a3.z) * inv, (a0.w + a1.w + a2.w + a3.w) * inv);
}

// bf16 gather aggregation (layer 0, halves gather bytes); 8-wide unroll
__global__ void agg_kernel_b(const __nv_bfloat16* __restrict__ hb, const int* __restrict__ rp,
                             const int* __restrict__ deg, const int* __restrict__ es,
                             float* __restrict__ hn, int ndst) {
    int lane = threadIdx.x & 31;
    int w = (blockIdx.x * blockDim.x + threadIdx.x) >> 5;
    if (w >= ndst) return;
    int start = rp[w];
    int cnt = deg[w];
    float4 a0 = make_float4(0.f, 0.f, 0.f, 0.f);
    float4 a1 = make_float4(0.f, 0.f, 0.f, 0.f);
    float4 a2 = make_float4(0.f, 0.f, 0.f, 0.f);
    float4 a3 = make_float4(0.f, 0.f, 0.f, 0.f);
    const uint2* h2 = reinterpret_cast<const uint2*>(hb);
#define ACC_B(aa, u) do { \
        __nv_bfloat162 p0 = *reinterpret_cast<__nv_bfloat162*>(&(u).x); \
        __nv_bfloat162 p1 = *reinterpret_cast<__nv_bfloat162*>(&(u).y); \
        float2 f0 = __bfloat1622float2(p0); \
        float2 f1 = __bfloat1622float2(p1); \
        aa.x += f0.x; aa.y += f0.y; aa.z += f1.x; aa.w += f1.y; \
    } while (0)
    for (int base = 0; base < cnt; base += 32) {
        int n = min(32, cnt - base);
        int sidx = (lane < n) ? es[start + base + lane] : 0;
        int j = 0;
        for (; j + 8 <= n; j += 8) {
            int s0 = __shfl_sync(0xffffffffu, sidx, j);
            int s1 = __shfl_sync(0xffffffffu, sidx, j + 1);
            int s2 = __shfl_sync(0xffffffffu, sidx, j + 2);
            int s3 = __shfl_sync(0xffffffffu, sidx, j + 3);
            int s4 = __shfl_sync(0xffffffffu, sidx, j + 4);
            int s5 = __shfl_sync(0xffffffffu, sidx, j + 5);
            int s6 = __shfl_sync(0xffffffffu, sidx, j + 6);
            int s7 = __shfl_sync(0xffffffffu, sidx, j + 7);
            uint2 u0 = h2[(size_t)s0 * 32 + lane];
            uint2 u1 = h2[(size_t)s1 * 32 + lane];
            uint2 u2 = h2[(size_t)s2 * 32 + lane];
            uint2 u3 = h2[(size_t)s3 * 32 + lane];
            uint2 u4 = h2[(size_t)s4 * 32 + lane];
            uint2 u5 = h2[(size_t)s5 * 32 + lane];
            uint2 u6 = h2[(size_t)s6 * 32 + lane];
            uint2 u7 = h2[(size_t)s7 * 32 + lane];
            ACC_B(a0, u0); ACC_B(a1, u1); ACC_B(a2, u2); ACC_B(a3, u3);
            ACC_B(a0, u4); ACC_B(a1, u5); ACC_B(a2, u6); ACC_B(a3, u7);
        }
        for (; j < n; j++) {
            int s0 = __shfl_sync(0xffffffffu, sidx, j);
            uint2 u0 = h2[(size_t)s0 * 32 + lane];
            ACC_B(a0, u0);
        }
    }
#undef ACC_B
    float inv = 1.0f / (float)max(cnt, 1);
    reinterpret_cast<float4*>(hn)[(size_t)w * 32 + lane] =
        make_float4((a0.x + a1.x + a2.x + a3.x) * inv, (a0.y + a1.y + a2.y + a3.y) * inv,
                    (a0.z + a1.z + a2.z + a3.z) * inv, (a0.w + a1.w + a2.w + a3.w) * inv);
}

// ---------------- launch ----------------
extern "C" void kernel_launch(void* const* d_in, const int* in_sizes, int n_in,
                              void* d_out, int out_size) {
    const float* feat    = (const float*)d_in[0];
    const int*   src0    = (const int*)d_in[1];
    const int*   dst0    = (const int*)d_in[2];
    const int*   src1    = (const int*)d_in[3];
    const int*   dst1    = (const int*)d_in[4];
    const float* W_init  = (const float*)d_in[5];
    const float* b_init  = (const float*)d_in[6];
    const float* W_self  = (const float*)d_in[7];
    const float* b_self  = (const float*)d_in[8];
    const float* W_neigh = (const float*)d_in[9];
    const float* b_neigh = (const float*)d_in[10];
    float* out = (float*)d_out;

    float *h0, *h1, *hn0, *hn1;
    __nv_bfloat16 *h0b;
    __nv_bfloat16 *WiH, *WiL, *WsH, *WsL, *WnH, *WnL;
    int *deg0, *rp0, *cur0, *es0, *deg1, *rp1, *cur1, *es1, *incl, *btot;
    cudaGetSymbolAddress((void**)&h0,  g_h0);
    cudaGetSymbolAddress((void**)&h0b, g_h0b);
    cudaGetSymbolAddress((void**)&h1,  g_h1);
    cudaGetSymbolAddress((void**)&hn0, g_hn0);
    cudaGetSymbolAddress((void**)&hn1, g_hn1);
    cudaGetSymbolAddress((void**)&WiH, g_WiH);
    cudaGetSymbolAddress((void**)&WiL, g_WiL);
    cudaGetSymbolAddress((void**)&WsH, g_WsH);
    cudaGetSymbolAddress((void**)&WsL, g_WsL);
    cudaGetSymbolAddress((void**)&WnH, g_WnH);
    cudaGetSymbolAddress((void**)&WnL, g_WnL);
    cudaGetSymbolAddress((void**)&deg0, g_deg0);
    cudaGetSymbolAddress((void**)&rp0,  g_rp0);
    cudaGetSymbolAddress((void**)&cur0, g_cur0);
    cudaGetSymbolAddress((void**)&es0,  g_es0);
    cudaGetSymbolAddress((void**)&deg1, g_deg1);
    cudaGetSymbolAddress((void**)&rp1,  g_rp1);
    cudaGetSymbolAddress((void**)&cur1, g_cur1);
    cudaGetSymbolAddress((void**)&es1,  g_es1);
    cudaGetSymbolAddress((void**)&incl, g_incl);
    cudaGetSymbolAddress((void**)&btot, g_btot);

    cudaFuncSetAttribute(gemm_mma<true, false, true>,
                         cudaFuncAttributeMaxDynamicSharedMemorySize, SMEM_TOTAL);
    cudaFuncSetAttribute(gemm_mma<true, true, false>,
                         cudaFuncAttributeMaxDynamicSharedMemorySize, SMEM_TOTAL);
    cudaFuncSetAttribute(gemm_mma<false, true, false>,
                         cudaFuncAttributeMaxDynamicSharedMemorySize, SMEM_TOTAL);

    // side stream + events (created once on the first, non-captured call)
    static cudaStream_t sA = nullptr;
    static cudaEvent_t evFork = nullptr, ev0 = nullptr, ev1 = nullptr;
    if (!sA) {
        cudaStreamCreateWithFlags(&sA, cudaStreamNonBlocking);
        cudaEventCreateWithFlags(&evFork, cudaEventDisableTiming);
        cudaEventCreateWithFlags(&ev0, cudaEventDisableTiming);
        cudaEventCreateWithFlags(&ev1, cudaEventDisableTiming);
    }

    const int NB0 = (N_DST0 + 1023) / 1024;   // 49
    const int NB1 = (N_DST1 + 1023) / 1024;   // 10

    // ---- fork: CSR builds run on sA concurrent with wprep/gemm1 ----
    cudaEventRecord(evFork, 0);
    cudaStreamWaitEvent(sA, evFork, 0);

    cudaMemsetAsync(deg0, 0, N_DST0 * sizeof(int), sA);
    hist_kernel<<<(E0 + 255) / 256, 256, 0, sA>>>(dst0, deg0, E0);
    scan_pass1<<<NB0, 1024, 0, sA>>>(deg0, incl, btot, N_DST0);
    scan_pass2<<<1, 64, 0, sA>>>(btot, NB0);
    scan_pass3<<<NB0, 1024, 0, sA>>>(incl, deg0, btot, rp0, cur0, N_DST0);
    fill_kernel<<<(E0 + 255) / 256, 256, 0, sA>>>(src0, dst0, cur0, es0, E0);
    cudaEventRecord(ev0, sA);
    cudaMemsetAsync(deg1, 0, N_DST1 * sizeof(int), sA);
    hist_kernel<<<(E1 + 255) / 256, 256, 0, sA>>>(dst1, deg1, E1);
    scan_pass1<<<NB1, 1024, 0, sA>>>(deg1, incl, btot, N_DST1);
    scan_pass2<<<1, 64, 0, sA>>>(btot, NB1);
    scan_pass3<<<NB1, 1024, 0, sA>>>(incl, deg1, btot, rp1, cur1, N_DST1);
    fill_kernel<<<(E1 + 255) / 256, 256, 0, sA>>>(src1, dst1, cur1, es1, E1);
    cudaEventRecord(ev1, sA);

    // main: weight prep + fc_init GEMM  h0 = relu(feat@Wi + bi)  (+ bf16 copy)
    wprep_kernel<<<192, 256>>>(W_init, W_self, W_neigh, WiH, WiL, WsH, WsL, WnH, WnL);
    gemm_mma<true, false, true><<<(N_SRC0 + 63) / 64, 128, SMEM_TOTAL>>>(
        feat, nullptr, WiH, WiL, nullptr, nullptr, b_init, nullptr, h0, h0b, N_SRC0);

    // join CSR0, aggregate (bf16 gather), dual GEMM
    cudaStreamWaitEvent(0, ev0, 0);
    agg_kernel_b<<<N_DST0 / 8, 256>>>(h0b, rp0, deg0, es0, hn0, N_DST0);
    gemm_mma<true, true, false><<<(N_DST0 + 63) / 64, 128, SMEM_TOTAL>>>(
        h0, hn0, WsH, WsL, WnH, WnL, b_self, b_neigh, h1, nullptr, N_DST0);

    // join CSR1, aggregate (fp32), dual GEMM
    cudaStreamWaitEvent(0, ev1, 0);
    agg_kernel<<<N_DST1 / 8, 256>>>(h1, rp1, deg1, es1, hn1, N_DST1);
    gemm_mma<false, true, false><<<(N_DST1 + 63) / 64, 128, SMEM_TOTAL>>>(
        h1, hn1, WsH, WsL, WnH, WnL, b_self, b_neigh, out, nullptr, N_DST1);
}

// round 10
// speedup vs baseline: 1.1442x; 1.0847x over previous
#include <cuda_runtime.h>
#include <cuda_bf16.h>
#include <cstdint>

// ---------------- problem sizes ----------------
#define N_SRC0 200000
#define N_DST0 50000
#define N_DST1 10000
#define E0     800000
#define E1     160000
#define D      128

// ---------------- scratch (device globals; no allocs allowed) ----------------
__device__ float g_h0[(size_t)N_SRC0 * D];
__device__ float g_h1[(size_t)N_DST0 * D];
__device__ float g_hn0[(size_t)N_DST0 * D];
__device__ float g_hn1[(size_t)N_DST1 * D];
// transposed bf16 weight images Wt[n][k] = W[k][n], hi/lo split
__device__ __align__(16) __nv_bfloat16 g_WiH[16384], g_WiL[16384];
__device__ __align__(16) __nv_bfloat16 g_WsH[16384], g_WsL[16384];
__device__ __align__(16) __nv_bfloat16 g_WnH[16384], g_WnL[16384];
__device__ int g_deg0[N_DST0], g_rp0[N_DST0], g_cur0[N_DST0];
__device__ int g_deg1[N_DST1], g_rp1[N_DST1], g_cur1[N_DST1];
__device__ int g_es0[E0], g_es1[E1];
__device__ int g_incl[N_DST0];
__device__ int g_btot[64];

// ---------------- helpers ----------------
__device__ __forceinline__ uint32_t smem_to_u32(const void* p) {
    uint32_t a;
    asm("{ .reg .u64 t; cvta.to.shared.u64 t, %1; cvt.u32.u64 %0, t; }" : "=r"(a) : "l"(p));
    return a;
}

#define LDMATRIX_X4(r0, r1, r2, r3, addr) \
    asm volatile("ldmatrix.sync.aligned.m8n8.x4.shared.b16 {%0,%1,%2,%3}, [%4];" \
                 : "=r"(r0), "=r"(r1), "=r"(r2), "=r"(r3) : "r"(addr))

#define MMA_BF16(d, a, bv0, bv1) \
    asm volatile("mma.sync.aligned.m16n8k16.row.col.f32.bf16.bf16.f32 " \
                 "{%0,%1,%2,%3}, {%4,%5,%6,%7}, {%8,%9}, {%0,%1,%2,%3};" \
                 : "+f"((d)[0]), "+f"((d)[1]), "+f"((d)[2]), "+f"((d)[3]) \
                 : "r"((a)[0]), "r"((a)[1]), "r"((a)[2]), "r"((a)[3]), \
                   "r"(bv0), "r"(bv1))

#define CP_ASYNC16(dst, src) \
    asm volatile("cp.async.cg.shared.global [%0], [%1], 16;" :: "r"(dst), "l"(src))
#define CP_COMMIT() asm volatile("cp.async.commit_group;")
#define CP_WAIT0()  asm volatile("cp.async.wait_group 0;" ::: "memory")

// split a float4 into bf16 hi/lo packed words
__device__ __forceinline__ void split_f4(float4 v, uint2& hw, uint2& lw) {
    __nv_bfloat162 h01 = __float22bfloat162_rn(make_float2(v.x, v.y));
    __nv_bfloat162 h23 = __float22bfloat162_rn(make_float2(v.z, v.w));
    float2 f01 = __bfloat1622float2(h01);
    float2 f23 = __bfloat1622float2(h23);
    __nv_bfloat162 l01 = __float22bfloat162_rn(make_float2(v.x - f01.x, v.y - f01.y));
    __nv_bfloat162 l23 = __float22bfloat162_rn(make_float2(v.z - f23.x, v.w - f23.y));
    hw.x = *reinterpret_cast<uint32_t*>(&h01);
    hw.y = *reinterpret_cast<uint32_t*>(&h23);
    lw.x = *reinterpret_cast<uint32_t*>(&l01);
    lw.y = *reinterpret_cast<uint32_t*>(&l23);
}

// ---------------- weight image prep (one launch for all 3) ----------------
__global__ void wprep_kernel(const float* __restrict__ Wi, const float* __restrict__ Ws,
                             const float* __restrict__ Wn,
                             __nv_bfloat16* __restrict__ WiH, __nv_bfloat16* __restrict__ WiL,
                             __nv_bfloat16* __restrict__ WsH, __nv_bfloat16* __restrict__ WsL,
                             __nv_bfloat16* __restrict__ WnH, __nv_bfloat16* __restrict__ WnL) {
    int bid = blockIdx.x;
    const float* W = (bid < 64) ? Wi : (bid < 128) ? Ws : Wn;
    __nv_bfloat16* H = (bid < 64) ? WiH : (bid < 128) ? WsH : WnH;
    __nv_bfloat16* L = (bid < 64) ? WiL : (bid < 128) ? WsL : WnL;
    int idx = (bid & 63) * 256 + threadIdx.x;
    int n = idx >> 7, k = idx & 127;
    float w = W[k * 128 + n];
    __nv_bfloat16 h = __float2bfloat16(w);
    __nv_bfloat16 l = __float2bfloat16(w - __bfloat162float(h));
    H[idx] = h;
    L[idx] = l;
}

#define SA 136

// =========== persistent double-buffered GEMM for fc_init (BM=128, BN=128) ===========
#define P_BIAS 0
#define P_WH   512
#define P_WL   (P_WH + 128 * SA * 2)          // 35328
#define P_A    (P_WL + 128 * SA * 2)          // 70144; two bufs of (AH+AL)=69632
#define P_ABUF (128 * SA * 2 * 2)             // 69632
#define P_SMEM (P_A + 2 * P_ABUF)             // 209408

__global__ void __launch_bounds__(256)
gemm_persist(const float* __restrict__ A, const __nv_bfloat16* __restrict__ Wh,
             const __nv_bfloat16* __restrict__ Wl, const float* __restrict__ bias,
             float* __restrict__ out, int M, int ntiles)
{
    extern __shared__ char smem[];
    float* sbias = reinterpret_cast<float*>(smem + P_BIAS);
    const uint32_t sb = smem_to_u32(smem);
    const int tid = threadIdx.x;
    const int wid = tid >> 5;
    const int lane = tid & 31;
    const int warp_m = wid & 3;     // 4 warps over M (32 rows each)
    const int warp_n = wid >> 2;    // 2 warps over N (64 cols each)

    if (tid < 128) sbias[tid] = bias[tid];

    // stage W hi/lo via cp.async
    {
        const uint4* gh = reinterpret_cast<const uint4*>(Wh);
        const uint4* gl = reinterpret_cast<const uint4*>(Wl);
#pragma unroll
        for (int it = 0; it < 8; it++) {
            int idx = it * 256 + tid;
            int r = idx >> 4, wg = idx & 15;
            uint32_t d = (uint32_t)(r * SA + wg * 8) * 2;
            CP_ASYNC16(sb + P_WH + d, gh + idx);
            CP_ASYNC16(sb + P_WL + d, gl + idx);
        }
        CP_COMMIT();
    }

    const int tl = lane >> 3, trow = lane & 7;
    uint32_t aoff[2], boff[4];
#pragma unroll
    for (int mi = 0; mi < 2; mi++) {
        int row = warp_m * 32 + mi * 16 + trow + (tl & 1) * 8;
        int col = (tl >> 1) * 8;
        aoff[mi] = (uint32_t)(row * SA + col) * 2;
    }
#pragma unroll
    for (int nh = 0; nh < 4; nh++) {
        int n = warp_n * 64 + nh * 16 + (tl >> 1) * 8 + trow;
        int col = (tl & 1) * 8;
        boff[nh] = (uint32_t)(n * SA + col) * 2;
    }

    int t = blockIdx.x;
    if (t >= ntiles) return;
    const int stride = gridDim.x;

    // prologue: convert tile t into buffer 0
    {
        int tbase = t * 128;
#pragma unroll
        for (int it = 0; it < 16; it++) {
            int e = it * 256 + tid;
            int row = e >> 5, c4 = e & 31;
            int grow = tbase + row;
            float4 v = make_float4(0.f, 0.f, 0.f, 0.f);
            if (grow < M)
                v = *reinterpret_cast<const float4*>(A + (size_t)grow * D + c4 * 4);
            uint2 hw, lw;
            split_f4(v, hw, lw);
            uint32_t d = (uint32_t)(row * SA + c4 * 4) * 2;
            *reinterpret_cast<uint2*>(smem + P_A + d) = hw;
            *reinterpret_cast<uint2*>(smem + P_A + 128 * SA * 2 + d) = lw;
        }
    }
    CP_WAIT0();

    int cur = 0;
    while (t < ntiles) {
        __syncthreads();
        int next = t + stride;
        bool hasnext = next < ntiles;

        // prefetch next tile's fp32 rows into registers (latency hides under MMA)
        float4 st[16];
        if (hasnext) {
            int nbase = next * 128;
#pragma unroll
            for (int it = 0; it < 16; it++) {
                int e = it * 256 + tid;
                int row = e >> 5, c4 = e & 31;
                int grow = nbase + row;
                st[it] = make_float4(0.f, 0.f, 0.f, 0.f);
                if (grow < M)
                    st[it] = *reinterpret_cast<const float4*>(A + (size_t)grow * D + c4 * 4);
            }
        }

        // MMA over K=128 from buffer cur
        float acc[2][8][4];
#pragma unroll
        for (int i = 0; i < 2; i++)
#pragma unroll
            for (int j = 0; j < 8; j++)
#pragma unroll
                for (int r = 0; r < 4; r++) acc[i][j][r] = 0.f;

        const uint32_t abase = sb + P_A + cur * P_ABUF;
        const uint32_t albase = abase + 128 * SA * 2;
#pragma unroll
        for (int ks = 0; ks < 8; ks++) {
            const uint32_t kb = ks * 32;
            uint32_t bh[16], bl[16];
#pragma unroll
            for (int nh = 0; nh < 4; nh++) {
                LDMATRIX_X4(bh[nh * 4], bh[nh * 4 + 1], bh[nh * 4 + 2], bh[nh * 4 + 3],
                            sb + P_WH + boff[nh] + kb);
                LDMATRIX_X4(bl[nh * 4], bl[nh * 4 + 1], bl[nh * 4 + 2], bl[nh * 4 + 3],
                            sb + P_WL + boff[nh] + kb);
            }
#pragma unroll
            for (int mi = 0; mi < 2; mi++) {
                uint32_t ah[4], al[4];
                LDMATRIX_X4(ah[0], ah[1], ah[2], ah[3], abase + aoff[mi] + kb);
                LDMATRIX_X4(al[0], al[1], al[2], al[3], albase + aoff[mi] + kb);
#pragma unroll
                for (int nj = 0; nj < 8; nj++) {
                    int bi = (nj >> 1) * 4 + (nj & 1) * 2;
                    MMA_BF16(acc[mi][nj], ah, bh[bi], bh[bi + 1]);
                    MMA_BF16(acc[mi][nj], al, bh[bi], bh[bi + 1]);
                    MMA_BF16(acc[mi][nj], ah, bl[bi], bl[bi + 1]);
                }
            }
        }

        // epilogue: bias + relu + store
        {
            int tbase = t * 128;
            const int g = lane >> 2, t2 = lane & 3;
#pragma unroll
            for (int mi = 0; mi < 2; mi++) {
                int row0 = tbase + warp_m * 32 + mi * 16 + g;
                int row1 = row0 + 8;
#pragma unroll
                for (int nj = 0; nj < 8; nj++) {
                    int col = warp_n * 64 + nj * 8 + t2 * 2;
                    float bx = sbias[col], by = sbias[col + 1];
                    float2 v0 = make_float2(fmaxf(acc[mi][nj][0] + bx, 0.f),
                                            fmaxf(acc[mi][nj][1] + by, 0.f));
                    float2 v1 = make_float2(fmaxf(acc[mi][nj][2] + bx, 0.f),
                                            fmaxf(acc[mi][nj][3] + by, 0.f));
                    if (row0 < M)
                        *reinterpret_cast<float2*>(out + (size_t)row0 * D + col) = v0;
                    if (row1 < M)
                        *reinterpret_cast<float2*>(out + (size_t)row1 * D + col) = v1;
                }
            }
        }

        // convert prefetched tile into the other buffer
        if (hasnext) {
            uint32_t dsth = P_A + (cur ^ 1) * P_ABUF;
            uint32_t dstl = dsth + 128 * SA * 2;
#pragma unroll
            for (int it = 0; it < 16; it++) {
                int e = it * 256 + tid;
                int row = e >> 5, c4 = e & 31;
                uint2 hw, lw;
                split_f4(st[it], hw, lw);
                uint32_t d = (uint32_t)(row * SA + c4 * 4) * 2;
                *reinterpret_cast<uint2*>(smem + dsth + d) = hw;
                *reinterpret_cast<uint2*>(smem + dstl + d) = lw;
            }
        }
        cur ^= 1;
        t = next;
    }
}

// ---------------- non-persistent dual GEMM (layers 1-2, BM=64) ----------------
#define OFF_BIAS 0
#define OFF_AH   512
#define OFF_AL   (OFF_AH + 64 * SA * 2)
#define OFF_WH   (OFF_AL + 64 * SA * 2)
#define OFF_WL   (OFF_WH + 128 * SA * 2)
#define SMEM_TOTAL (OFF_WL + 128 * SA * 2)

template <bool RELU, bool DUAL>
__global__ void __launch_bounds__(128)
gemm_mma(const float* __restrict__ A0, const float* __restrict__ A1,
         const __nv_bfloat16* __restrict__ W0h, const __nv_bfloat16* __restrict__ W0l,
         const __nv_bfloat16* __restrict__ W1h, const __nv_bfloat16* __restrict__ W1l,
         const float* __restrict__ b0, const float* __restrict__ b1,
         float* __restrict__ out, int M)
{
    extern __shared__ char smem[];
    float* sbias = reinterpret_cast<float*>(smem + OFF_BIAS);
    const uint32_t sb = smem_to_u32(smem);
    const int tid = threadIdx.x;
    const int wid = tid >> 5;
    const int lane = tid & 31;
    const int warp_m = wid & 1;
    const int warp_n = wid >> 1;
    const int rowBase = blockIdx.x * 64;

    if (tid < 128) {
        float b = b0[tid];
        if (DUAL) b += b1[tid];
        sbias[tid] = b;
    }

    float acc[2][8][4];
#pragma unroll
    for (int i = 0; i < 2; i++)
#pragma unroll
        for (int j = 0; j < 8; j++)
#pragma unroll
            for (int r = 0; r < 4; r++) acc[i][j][r] = 0.f;

    const int tl = lane >> 3, trow = lane & 7;
    uint32_t aoff[2], boff[4];
#pragma unroll
    for (int mi = 0; mi < 2; mi++) {
        int row = warp_m * 32 + mi * 16 + trow + (tl & 1) * 8;
        int col = (tl >> 1) * 8;
        aoff[mi] = (uint32_t)(row * SA + col) * 2;
    }
#pragma unroll
    for (int nh = 0; nh < 4; nh++) {
        int n = warp_n * 64 + nh * 16 + (tl >> 1) * 8 + trow;
        int col = (tl & 1) * 8;
        boff[nh] = (uint32_t)(n * SA + col) * 2;
    }

    const int npass = DUAL ? 2 : 1;
#pragma unroll 1
    for (int pass = 0; pass < npass; ++pass) {
        const float* A = pass ? A1 : A0;
        const __nv_bfloat16* Wh = pass ? W1h : W0h;
        const __nv_bfloat16* Wl = pass ? W1l : W0l;

        {
            const uint4* gh = reinterpret_cast<const uint4*>(Wh);
            const uint4* gl = reinterpret_cast<const uint4*>(Wl);
#pragma unroll
            for (int it = 0; it < 16; it++) {
                int idx = it * 128 + tid;
                int r = idx >> 4, wg = idx & 15;
                uint32_t d = (uint32_t)(r * SA + wg * 8) * 2;
                CP_ASYNC16(sb + OFF_WH + d, gh + idx);
                CP_ASYNC16(sb + OFF_WL + d, gl + idx);
            }
            CP_COMMIT();
        }
#pragma unroll
        for (int it = 0; it < 16; it++) {
            int e = it * 128 + tid;
            int row = e >> 5, c4 = e & 31;
            int grow = rowBase + row;
            float4 v = make_float4(0.f, 0.f, 0.f, 0.f);
            if (grow < M)
                v = *reinterpret_cast<const float4*>(A + (size_t)grow * D + c4 * 4);
            uint2 hw, lw;
            split_f4(v, hw, lw);
            uint32_t d = (uint32_t)(row * SA + c4 * 4) * 2;
            *reinterpret_cast<uint2*>(smem + OFF_AH + d) = hw;
            *reinterpret_cast<uint2*>(smem + OFF_AL + d) = lw;
        }
        CP_WAIT0();
        __syncthreads();

#pragma unroll
        for (int ks = 0; ks < 8; ks++) {
            const uint32_t kb = ks * 32;
            uint32_t bh[16], bl[16];
#pragma unroll
            for (int nh = 0; nh < 4; nh++) {
                LDMATRIX_X4(bh[nh * 4], bh[nh * 4 + 1], bh[nh * 4 + 2], bh[nh * 4 + 3],
                            sb + OFF_WH + boff[nh] + kb);
                LDMATRIX_X4(bl[nh * 4], bl[nh * 4 + 1], bl[nh * 4 + 2], bl[nh * 4 + 3],
                            sb + OFF_WL + boff[nh] + kb);
            }
#pragma unroll
            for (int mi = 0; mi < 2; mi++) {
                uint32_t ah[4], al[4];
                LDMATRIX_X4(ah[0], ah[1], ah[2], ah[3], sb + OFF_AH + aoff[mi] + kb);
                LDMATRIX_X4(al[0], al[1], al[2], al[3], sb + OFF_AL + aoff[mi] + kb);
#pragma unroll
                for (int nj = 0; nj < 8; nj++) {
                    int bi = (nj >> 1) * 4 + (nj & 1) * 2;
                    MMA_BF16(acc[mi][nj], ah, bh[bi], bh[bi + 1]);
                    MMA_BF16(acc[mi][nj], al, bh[bi], bh[bi + 1]);
                    MMA_BF16(acc[mi][nj], ah, bl[bi], bl[bi + 1]);
                }
            }
        }
        __syncthreads();
    }

    const int g = lane >> 2, t = lane & 3;
#pragma unroll
    for (int mi = 0; mi < 2; mi++) {
        int row0 = rowBase + warp_m * 32 + mi * 16 + g;
        int row1 = row0 + 8;
#pragma unroll
        for (int nj = 0; nj < 8; nj++) {
            int col = warp_n * 64 + nj * 8 + t * 2;
            float bx = sbias[col], by = sbias[col + 1];
            float2 v0 = make_float2(acc[mi][nj][0] + bx, acc[mi][nj][1] + by);
            float2 v1 = make_float2(acc[mi][nj][2] + bx, acc[mi][nj][3] + by);
            if (RELU) {
                v0.x = fmaxf(v0.x, 0.f); v0.y = fmaxf(v0.y, 0.f);
                v1.x = fmaxf(v1.x, 0.f); v1.y = fmaxf(v1.y, 0.f);
            }
            if (row0 < M)
                *reinterpret_cast<float2*>(out + (size_t)row0 * D + col) = v0;
            if (row1 < M)
                *reinterpret_cast<float2*>(out + (size_t)row1 * D + col) = v1;
        }
    }
}

// ---------------- graph CSR build + mean aggregation ----------------
__global__ void hist_kernel(const int* __restrict__ dst, int* __restrict__ deg, int E) {
    int e = blockIdx.x * blockDim.x + threadIdx.x;
    if (e < E) atomicAdd(&deg[dst[e]], 1);
}

__global__ void scan_pass1(const int* __restrict__ deg, int* __restrict__ incl,
                           int* __restrict__ btot, int n) {
    __shared__ int wsum[32];
    int t = threadIdx.x;
    int i = blockIdx.x * 1024 + t;
    int v = (i < n) ? deg[i] : 0;
    int x = v;
#pragma unroll
    for (int o = 1; o < 32; o <<= 1) {
        int y = __shfl_up_sync(0xffffffffu, x, o);
        if ((t & 31) >= o) x += y;
    }
    if ((t & 31) == 31) wsum[t >> 5] = x;
    __syncthreads();
    if (t < 32) {
        int s = wsum[t];
#pragma unroll
        for (int o = 1; o < 32; o <<= 1) {
            int y = __shfl_up_sync(0xffffffffu, s, o);
            if (t >= o) s += y;
        }
        wsum[t] = s;
    }
    __syncthreads();
    int base = (t >= 32) ? wsum[(t >> 5) - 1] : 0;
    int inc = x + base;
    if (i < n) incl[i] = inc;
    if (t == 1023) btot[blockIdx.x] = inc;
}

__global__ void scan_pass2(int* __restrict__ btot, int nb) {
    __shared__ int s[64];
    int t = threadIdx.x;
    s[t] = (t < nb) ? btot[t] : 0;
    __syncthreads();
#pragma unroll
    for (int o = 1; o < 64; o <<= 1) {
        int v = (t >= o) ? s[t - o] : 0;
        __syncthreads();
        s[t] += v;
        __syncthreads();
    }
    if (t < nb) btot[t] = t ? s[t - 1] : 0;
}

__global__ void scan_pass3(const int* __restrict__ incl, const int* __restrict__ deg,
                           const int* __restrict__ btot, int* __restrict__ rp,
                           int* __restrict__ cur, int n) {
    int i = blockIdx.x * 1024 + threadIdx.x;
    if (i < n) {
        int r = btot[blockIdx.x] + incl[i] - deg[i];
        rp[i] = r;
        cur[i] = r;
    }
}

__global__ void fill_kernel(const int* __restrict__ src, const int* __restrict__ dst,
                            int* __restrict__ cur, int* __restrict__ es, int E) {
    int e = blockIdx.x * blockDim.x + threadIdx.x;
    if (e < E) {
        int p = atomicAdd(&cur[dst[e]], 1);
        es[p] = src[e];
    }
}

// one warp per dst node; 8-wide unrolled fp32 gather
__global__ void agg_kernel(const float* __restrict__ h, const int* __restrict__ rp,
                           const int* __restrict__ deg, const int* __restrict__ es,
                           float* __restrict__ hn, int ndst) {
    int lane = threadIdx.x & 31;
    int w = (blockIdx.x * blockDim.x + threadIdx.x) >> 5;
    if (w >= ndst) return;
    int start = rp[w];
    int cnt = deg[w];
    float4 a0 = make_float4(0.f, 0.f, 0.f, 0.f);
    float4 a1 = make_float4(0.f, 0.f, 0.f, 0.f);
    float4 a2 = make_float4(0.f, 0.f, 0.f, 0.f);
    float4 a3 = make_float4(0.f, 0.f, 0.f, 0.f);
    const float4* h4 = reinterpret_cast<const float4*>(h);
    for (int base = 0; base < cnt; base += 32) {
        int n = min(32, cnt - base);
        int sidx = (lane < n) ? es[start + base + lane] : 0;
        int j = 0;
        for (; j + 8 <= n; j += 8) {
            int s0 = __shfl_sync(0xffffffffu, sidx, j);
            int s1 = __shfl_sync(0xffffffffu, sidx, j + 1);
            int s2 = __shfl_sync(0xffffffffu, sidx, j + 2);
            int s3 = __shfl_sync(0xffffffffu, sidx, j + 3);
            int s4 = __shfl_sync(0xffffffffu, sidx, j + 4);
            int s5 = __shfl_sync(0xffffffffu, sidx, j + 5);
            int s6 = __shfl_sync(0xffffffffu, sidx, j + 6);
            int s7 = __shfl_sync(0xffffffffu, sidx, j + 7);
            float4 v0 = h4[(size_t)s0 * 32 + lane];
            float4 v1 = h4[(size_t)s1 * 32 + lane];
            float4 v2 = h4[(size_t)s2 * 32 + lane];
            float4 v3 = h4[(size_t)s3 * 32 + lane];
            float4 v4 = h4[(size_t)s4 * 32 + lane];
            float4 v5 = h4[(size_t)s5 * 32 + lane];
            float4 v6 = h4[(size_t)s6 * 32 + lane];
            float4 v7 = h4[(size_t)s7 * 32 + lane];
            a0.x += v0.x; a0.y += v0.y; a0.z += v0.z; a0.w += v0.w;
            a1.x += v1.x; a1.y += v1.y; a1.z += v1.z; a1.w += v1.w;
            a2.x += v2.x; a2.y += v2.y; a2.z += v2.z; a2.w += v2.w;
            a3.x += v3.x; a3.y += v3.y; a3.z += v3.z; a3.w += v3.w;
            a0.x += v4.x; a0.y += v4.y; a0.z += v4.z; a0.w += v4.w;
            a1.x += v5.x; a1.y += v5.y; a1.z += v5.z; a1.w += v5.w;
            a2.x += v6.x; a2.y += v6.y; a2.z += v6.z; a2.w += v6.w;
            a3.x += v7.x; a3.y += v7.y; a3.z += v7.z; a3.w += v7.w;
        }
        for (; j < n; j++) {
            int s0 = __shfl_sync(0xffffffffu, sidx, j);
            float4 v0 = h4[(size_t)s0 * 32 + lane];
            a0.x += v0.x; a0.y += v0.y; a0.z += v0.z; a0.w += v0.w;
        }
    }
    float inv = 1.0f / (float)max(cnt, 1);
    reinterpret_cast<float4*>(hn)[(size_t)w * 32 + lane] =
        make_float4((a0.x + a1.x + a2.x + a3.x) * inv, (a0.y + a1.y + a2.y + a3.y) * inv,
                    (a0.z + a1.z + a2.z + a3.z) * inv, (a0.w + a1.w + a2.w + a3.w) * inv);
}

// ---------------- launch ----------------
extern "C" void kernel_launch(void* const* d_in, const int* in_sizes, int n_in,
                              void* d_out, int out_size) {
    const float* feat    = (const float*)d_in[0];
    const int*   src0    = (const int*)d_in[1];
    const int*   dst0    = (const int*)d_in[2];
    const int*   src1    = (const int*)d_in[3];
    const int*   dst1    = (const int*)d_in[4];
    const float* W_init  = (const float*)d_in[5];
    const float* b_init  = (const float*)d_in[6];
    const float* W_self  = (const float*)d_in[7];
    const float* b_self  = (const float*)d_in[8];
    const float* W_neigh = (const float*)d_in[9];
    const float* b_neigh = (const float*)d_in[10];
    float* out = (float*)d_out;

    float *h0, *h1, *hn0, *hn1;
    __nv_bfloat16 *WiH, *WiL, *WsH, *WsL, *WnH, *WnL;
    int *deg0, *rp0, *cur0, *es0, *deg1, *rp1, *cur1, *es1, *incl, *btot;
    cudaGetSymbolAddress((void**)&h0,  g_h0);
    cudaGetSymbolAddress((void**)&h1,  g_h1);
    cudaGetSymbolAddress((void**)&hn0, g_hn0);
    cudaGetSymbolAddress((void**)&hn1, g_hn1);
    cudaGetSymbolAddress((void**)&WiH, g_WiH);
    cudaGetSymbolAddress((void**)&WiL, g_WiL);
    cudaGetSymbolAddress((void**)&WsH, g_WsH);
    cudaGetSymbolAddress((void**)&WsL, g_WsL);
    cudaGetSymbolAddress((void**)&WnH, g_WnH);
    cudaGetSymbolAddress((void**)&WnL, g_WnL);
    cudaGetSymbolAddress((void**)&deg0, g_deg0);
    cudaGetSymbolAddress((void**)&rp0,  g_rp0);
    cudaGetSymbolAddress((void**)&cur0, g_cur0);
    cudaGetSymbolAddress((void**)&es0,  g_es0);
    cudaGetSymbolAddress((void**)&deg1, g_deg1);
    cudaGetSymbolAddress((void**)&rp1,  g_rp1);
    cudaGetSymbolAddress((void**)&cur1, g_cur1);
    cudaGetSymbolAddress((void**)&es1,  g_es1);
    cudaGetSymbolAddress((void**)&incl, g_incl);
    cudaGetSymbolAddress((void**)&btot, g_btot);

    cudaFuncSetAttribute(gemm_persist,
                         cudaFuncAttributeMaxDynamicSharedMemorySize, P_SMEM);
    cudaFuncSetAttribute(gemm_mma<true, true>,
                         cudaFuncAttributeMaxDynamicSharedMemorySize, SMEM_TOTAL);
    cudaFuncSetAttribute(gemm_mma<false, true>,
                         cudaFuncAttributeMaxDynamicSharedMemorySize, SMEM_TOTAL);

    static cudaStream_t sA = nullptr;
    static cudaEvent_t evFork = nullptr, ev0 = nullptr, ev1 = nullptr;
    static int nsm = 0;
    if (!sA) {
        cudaStreamCreateWithFlags(&sA, cudaStreamNonBlocking);
        cudaEventCreateWithFlags(&evFork, cudaEventDisableTiming);
        cudaEventCreateWithFlags(&ev0, cudaEventDisableTiming);
        cudaEventCreateWithFlags(&ev1, cudaEventDisableTiming);
        cudaDeviceGetAttribute(&nsm, cudaDevAttrMultiProcessorCount, 0);
    }

    const int NB0 = (N_DST0 + 1023) / 1024;   // 49
    const int NB1 = (N_DST1 + 1023) / 1024;   // 10
    const int NT1 = (N_SRC0 + 127) / 128;     // 1563

    // ---- fork: CSR builds run on sA concurrent with wprep/gemm1 ----
    cudaEventRecord(evFork, 0);
    cudaStreamWaitEvent(sA, evFork, 0);

    cudaMemsetAsync(deg0, 0, N_DST0 * sizeof(int), sA);
    hist_kernel<<<(E0 + 255) / 256, 256, 0, sA>>>(dst0, deg0, E0);
    scan_pass1<<<NB0, 1024, 0, sA>>>(deg0, incl, btot, N_DST0);
    scan_pass2<<<1, 64, 0, sA>>>(btot, NB0);
    scan_pass3<<<NB0, 1024, 0, sA>>>(incl, deg0, btot, rp0, cur0, N_DST0);
    fill_kernel<<<(E0 + 255) / 256, 256, 0, sA>>>(src0, dst0, cur0, es0, E0);
    cudaEventRecord(ev0, sA);
    cudaMemsetAsync(deg1, 0, N_DST1 * sizeof(int), sA);
    hist_kernel<<<(E1 + 255) / 256, 256, 0, sA>>>(dst1, deg1, E1);
    scan_pass1<<<NB1, 1024, 0, sA>>>(deg1, incl, btot, N_DST1);
    scan_pass2<<<1, 64, 0, sA>>>(btot, NB1);
    scan_pass3<<<NB1, 1024, 0, sA>>>(incl, deg1, btot, rp1, cur1, N_DST1);
    fill_kernel<<<(E1 + 255) / 256, 256, 0, sA>>>(src1, dst1, cur1, es1, E1);
    cudaEventRecord(ev1, sA);

    // main: weight prep + persistent fc_init GEMM  h0 = relu(feat@Wi + bi)
    wprep_kernel<<<192, 256>>>(W_init, W_self, W_neigh, WiH, WiL, WsH, WsL, WnH, WnL);
    gemm_persist<<<nsm, 256, P_SMEM>>>(feat, WiH, WiL, b_init, h0, N_SRC0, NT1);

    // join CSR0, aggregate, dual GEMM
    cudaStreamWaitEvent(0, ev0, 0);
    agg_kernel<<<N_DST0 / 8, 256>>>(h0, rp0, deg0, es0, hn0, N_DST0);
    gemm_mma<true, true><<<(N_DST0 + 63) / 64, 128, SMEM_TOTAL>>>(
        h0, hn0, WsH, WsL, WnH, WnL, b_self, b_neigh, h1, N_DST0);

    // join CSR1, aggregate, dual GEMM
    cudaStreamWaitEvent(0, ev1, 0);
    agg_kernel<<<N_DST1 / 8, 256>>>(h1, rp1, deg1, es1, hn1, N_DST1);
    gemm_mma<false, true><<<(N_DST1 + 63) / 64, 128, SMEM_TOTAL>>>(
        h1, hn1, WsH, WsL, WnH, WnL, b_self, b_neigh, out, N_DST1);
}

// round 12
// speedup vs baseline: 1.1704x; 1.0229x over previous
#include <cuda_runtime.h>
#include <cuda_bf16.h>
#include <cstdint>

// ---------------- problem sizes ----------------
#define N_SRC0 200000
#define N_DST0 50000
#define N_DST1 10000
#define E0     800000
#define E1     160000
#define D      128

// ---------------- scratch (device globals; no allocs allowed) ----------------
__device__ float g_h0[(size_t)N_SRC0 * D];
__device__ float g_h1[(size_t)N_DST0 * D];
__device__ float g_hn0[(size_t)N_DST0 * D];
__device__ float g_hn1[(size_t)N_DST1 * D];
// transposed bf16 weight images Wt[n][k] = W[k][n], hi/lo split
__device__ __align__(16) __nv_bfloat16 g_WiH[16384], g_WiL[16384];
__device__ __align__(16) __nv_bfloat16 g_WsH[16384], g_WsL[16384];
__device__ __align__(16) __nv_bfloat16 g_WnH[16384], g_WnL[16384];
__device__ int g_deg0[N_DST0], g_rp0[N_DST0], g_cur0[N_DST0];
__device__ int g_deg1[N_DST1], g_rp1[N_DST1], g_cur1[N_DST1];
__device__ int g_es0[E0], g_es1[E1];
__device__ int g_incl[N_DST0];
__device__ int g_btot[64];

// ---------------- helpers ----------------
__device__ __forceinline__ uint32_t smem_to_u32(const void* p) {
    uint32_t a;
    asm("{ .reg .u64 t; cvta.to.shared.u64 t, %1; cvt.u32.u64 %0, t; }" : "=r"(a) : "l"(p));
    return a;
}

#define LDMATRIX_X4(r0, r1, r2, r3, addr) \
    asm volatile("ldmatrix.sync.aligned.m8n8.x4.shared.b16 {%0,%1,%2,%3}, [%4];" \
                 : "=r"(r0), "=r"(r1), "=r"(r2), "=r"(r3) : "r"(addr))

#define MMA_BF16(d, a, bv0, bv1) \
    asm volatile("mma.sync.aligned.m16n8k16.row.col.f32.bf16.bf16.f32 " \
                 "{%0,%1,%2,%3}, {%4,%5,%6,%7}, {%8,%9}, {%0,%1,%2,%3};" \
                 : "+f"((d)[0]), "+f"((d)[1]), "+f"((d)[2]), "+f"((d)[3]) \
                 : "r"((a)[0]), "r"((a)[1]), "r"((a)[2]), "r"((a)[3]), \
                   "r"(bv0), "r"(bv1))

#define CP_ASYNC16(dst, src) \
    asm volatile("cp.async.cg.shared.global [%0], [%1], 16;" :: "r"(dst), "l"(src))
#define CP_COMMIT() asm volatile("cp.async.commit_group;")
#define CP_WAIT0()  asm volatile("cp.async.wait_group 0;" ::: "memory")

// split a float4 into bf16 hi/lo packed words
__device__ __forceinline__ void split_f4(float4 v, uint2& hw, uint2& lw) {
    __nv_bfloat162 h01 = __float22bfloat162_rn(make_float2(v.x, v.y));
    __nv_bfloat162 h23 = __float22bfloat162_rn(make_float2(v.z, v.w));
    float2 f01 = __bfloat1622float2(h01);
    float2 f23 = __bfloat1622float2(h23);
    __nv_bfloat162 l01 = __float22bfloat162_rn(make_float2(v.x - f01.x, v.y - f01.y));
    __nv_bfloat162 l23 = __float22bfloat162_rn(make_float2(v.z - f23.x, v.w - f23.y));
    hw.x = *reinterpret_cast<uint32_t*>(&h01);
    hw.y = *reinterpret_cast<uint32_t*>(&h23);
    lw.x = *reinterpret_cast<uint32_t*>(&l01);
    lw.y = *reinterpret_cast<uint32_t*>(&l23);
}

// ---------------- weight image prep (one launch for all 3) ----------------
__global__ void wprep_kernel(const float* __restrict__ Wi, const float* __restrict__ Ws,
                             const float* __restrict__ Wn,
                             __nv_bfloat16* __restrict__ WiH, __nv_bfloat16* __restrict__ WiL,
                             __nv_bfloat16* __restrict__ WsH, __nv_bfloat16* __restrict__ WsL,
                             __nv_bfloat16* __restrict__ WnH, __nv_bfloat16* __restrict__ WnL) {
    int bid = blockIdx.x;
    const float* W = (bid < 64) ? Wi : (bid < 128) ? Ws : Wn;
    __nv_bfloat16* H = (bid < 64) ? WiH : (bid < 128) ? WsH : WnH;
    __nv_bfloat16* L = (bid < 64) ? WiL : (bid < 128) ? WsL : WnL;
    int idx = (bid & 63) * 256 + threadIdx.x;
    int n = idx >> 7, k = idx & 127;
    float w = W[k * 128 + n];
    __nv_bfloat16 h = __float2bfloat16(w);
    __nv_bfloat16 l = __float2bfloat16(w - __bfloat162float(h));
    H[idx] = h;
    L[idx] = l;
}

#define SA 136

// =========== persistent double-buffered GEMM for fc_init (BM=128, BN=128) ===========
#define P_BIAS 0
#define P_WH   512
#define P_WL   (P_WH + 128 * SA * 2)
#define P_A    (P_WL + 128 * SA * 2)
#define P_ABUF (128 * SA * 2 * 2)
#define P_SMEM (P_A + 2 * P_ABUF)             // 209408

__global__ void __launch_bounds__(256)
gemm_persist(const float* __restrict__ A, const __nv_bfloat16* __restrict__ Wh,
             const __nv_bfloat16* __restrict__ Wl, const float* __restrict__ bias,
             float* __restrict__ out, int M, int ntiles)
{
    extern __shared__ char smem[];
    float* sbias = reinterpret_cast<float*>(smem + P_BIAS);
    const uint32_t sb = smem_to_u32(smem);
    const int tid = threadIdx.x;
    const int wid = tid >> 5;
    const int lane = tid & 31;
    const int warp_m = wid & 3;
    const int warp_n = wid >> 2;

    if (tid < 128) sbias[tid] = bias[tid];

    {
        const uint4* gh = reinterpret_cast<const uint4*>(Wh);
        const uint4* gl = reinterpret_cast<const uint4*>(Wl);
#pragma unroll
        for (int it = 0; it < 8; it++) {
            int idx = it * 256 + tid;
            int r = idx >> 4, wg = idx & 15;
            uint32_t d = (uint32_t)(r * SA + wg * 8) * 2;
            CP_ASYNC16(sb + P_WH + d, gh + idx);
            CP_ASYNC16(sb + P_WL + d, gl + idx);
        }
        CP_COMMIT();
    }

    const int tl = lane >> 3, trow = lane & 7;
    uint32_t aoff[2], boff[4];
#pragma unroll
    for (int mi = 0; mi < 2; mi++) {
        int row = warp_m * 32 + mi * 16 + trow + (tl & 1) * 8;
        int col = (tl >> 1) * 8;
        aoff[mi] = (uint32_t)(row * SA + col) * 2;
    }
#pragma unroll
    for (int nh = 0; nh < 4; nh++) {
        int n = warp_n * 64 + nh * 16 + (tl >> 1) * 8 + trow;
        int col = (tl & 1) * 8;
        boff[nh] = (uint32_t)(n * SA + col) * 2;
    }

    int t = blockIdx.x;
    if (t >= ntiles) return;
    const int stride = gridDim.x;

    {
        int tbase = t * 128;
#pragma unroll
        for (int it = 0; it < 16; it++) {
            int e = it * 256 + tid;
            int row = e >> 5, c4 = e & 31;
            int grow = tbase + row;
            float4 v = make_float4(0.f, 0.f, 0.f, 0.f);
            if (grow < M)
                v = *reinterpret_cast<const float4*>(A + (size_t)grow * D + c4 * 4);
            uint2 hw, lw;
            split_f4(v, hw, lw);
            uint32_t d = (uint32_t)(row * SA + c4 * 4) * 2;
            *reinterpret_cast<uint2*>(smem + P_A + d) = hw;
            *reinterpret_cast<uint2*>(smem + P_A + 128 * SA * 2 + d) = lw;
        }
    }
    CP_WAIT0();

    int cur = 0;
    while (t < ntiles) {
        __syncthreads();
        int next = t + stride;
        bool hasnext = next < ntiles;

        float4 st[16];
        if (hasnext) {
            int nbase = next * 128;
#pragma unroll
            for (int it = 0; it < 16; it++) {
                int e = it * 256 + tid;
                int row = e >> 5, c4 = e & 31;
                int grow = nbase + row;
                st[it] = make_float4(0.f, 0.f, 0.f, 0.f);
                if (grow < M)
                    st[it] = *reinterpret_cast<const float4*>(A + (size_t)grow * D + c4 * 4);
            }
        }

        float acc[2][8][4];
#pragma unroll
        for (int i = 0; i < 2; i++)
#pragma unroll
            for (int j = 0; j < 8; j++)
#pragma unroll
                for (int r = 0; r < 4; r++) acc[i][j][r] = 0.f;

        const uint32_t abase = sb + P_A + cur * P_ABUF;
        const uint32_t albase = abase + 128 * SA * 2;
#pragma unroll
        for (int ks = 0; ks < 8; ks++) {
            const uint32_t kb = ks * 32;
            uint32_t bh[16], bl[16];
#pragma unroll
            for (int nh = 0; nh < 4; nh++) {
                LDMATRIX_X4(bh[nh * 4], bh[nh * 4 + 1], bh[nh * 4 + 2], bh[nh * 4 + 3],
                            sb + P_WH + boff[nh] + kb);
                LDMATRIX_X4(bl[nh * 4], bl[nh * 4 + 1], bl[nh * 4 + 2], bl[nh * 4 + 3],
                            sb + P_WL + boff[nh] + kb);
            }
#pragma unroll
            for (int mi = 0; mi < 2; mi++) {
                uint32_t ah[4], al[4];
                LDMATRIX_X4(ah[0], ah[1], ah[2], ah[3], abase + aoff[mi] + kb);
                LDMATRIX_X4(al[0], al[1], al[2], al[3], albase + aoff[mi] + kb);
#pragma unroll
                for (int nj = 0; nj < 8; nj++) {
                    int bi = (nj >> 1) * 4 + (nj & 1) * 2;
                    MMA_BF16(acc[mi][nj], ah, bh[bi], bh[bi + 1]);
                    MMA_BF16(acc[mi][nj], al, bh[bi], bh[bi + 1]);
                    MMA_BF16(acc[mi][nj], ah, bl[bi], bl[bi + 1]);
                }
            }
        }

        {
            int tbase = t * 128;
            const int g = lane >> 2, t2 = lane & 3;
#pragma unroll
            for (int mi = 0; mi < 2; mi++) {
                int row0 = tbase + warp_m * 32 + mi * 16 + g;
                int row1 = row0 + 8;
#pragma unroll
                for (int nj = 0; nj < 8; nj++) {
                    int col = warp_n * 64 + nj * 8 + t2 * 2;
                    float bx = sbias[col], by = sbias[col + 1];
                    float2 v0 = make_float2(fmaxf(acc[mi][nj][0] + bx, 0.f),
                                            fmaxf(acc[mi][nj][1] + by, 0.f));
                    float2 v1 = make_float2(fmaxf(acc[mi][nj][2] + bx, 0.f),
                                            fmaxf(acc[mi][nj][3] + by, 0.f));
                    if (row0 < M)
                        *reinterpret_cast<float2*>(out + (size_t)row0 * D + col) = v0;
                    if (row1 < M)
                        *reinterpret_cast<float2*>(out + (size_t)row1 * D + col) = v1;
                }
            }
        }

        if (hasnext) {
            uint32_t dsth = P_A + (cur ^ 1) * P_ABUF;
            uint32_t dstl = dsth + 128 * SA * 2;
#pragma unroll
            for (int it = 0; it < 16; it++) {
                int e = it * 256 + tid;
                int row = e >> 5, c4 = e & 31;
                uint2 hw, lw;
                split_f4(st[it], hw, lw);
                uint32_t d = (uint32_t)(row * SA + c4 * 4) * 2;
                *reinterpret_cast<uint2*>(smem + dsth + d) = hw;
                *reinterpret_cast<uint2*>(smem + dstl + d) = lw;
            }
        }
        cur ^= 1;
        t = next;
    }
}

// ===== persistent dual GEMM (layers 1-2): out = act(A0@Ws + A1@Wn + bs + bn) =====
// BM=64, 128 threads; all 4 weight images resident; (tile, pass) pipeline.
#define Q_BIAS 0
#define Q_WSH  512
#define Q_WSL  (Q_WSH + 128 * SA * 2)
#define Q_WNH  (Q_WSL + 128 * SA * 2)
#define Q_WNL  (Q_WNH + 128 * SA * 2)
#define Q_A    (Q_WNL + 128 * SA * 2)          // 139776
#define Q_ABUF (64 * SA * 2 * 2)               // 34816 (AH+AL)
#define Q_SMEM (Q_A + 2 * Q_ABUF)              // 209408

template <bool RELU>
__global__ void __launch_bounds__(128)
gemm_persist_dual(const float* __restrict__ A0, const float* __restrict__ A1,
                  const __nv_bfloat16* __restrict__ WsH, const __nv_bfloat16* __restrict__ WsL,
                  const __nv_bfloat16* __restrict__ WnH, const __nv_bfloat16* __restrict__ WnL,
                  const float* __restrict__ b0, const float* __restrict__ b1,
                  float* __restrict__ out, int M, int ntiles)
{
    extern __shared__ char smem[];
    float* sbias = reinterpret_cast<float*>(smem + Q_BIAS);
    const uint32_t sb = smem_to_u32(smem);
    const int tid = threadIdx.x;
    const int wid = tid >> 5;
    const int lane = tid & 31;
    const int warp_m = wid & 1;     // 2 warps over M (32 rows each)
    const int warp_n = wid >> 1;    // 2 warps over N (64 cols each)

    if (tid < 128) sbias[tid] = b0[tid] + b1[tid];

    // stage all 4 weight images
    {
        const uint4* g0 = reinterpret_cast<const uint4*>(WsH);
        const uint4* g1 = reinterpret_cast<const uint4*>(WsL);
        const uint4* g2 = reinterpret_cast<const uint4*>(WnH);
        const uint4* g3 = reinterpret_cast<const uint4*>(WnL);
#pragma unroll
        for (int it = 0; it < 16; it++) {
            int idx = it * 128 + tid;            // 0..2047
            int r = idx >> 4, wg = idx & 15;
            uint32_t d = (uint32_t)(r * SA + wg * 8) * 2;
            CP_ASYNC16(sb + Q_WSH + d, g0 + idx);
            CP_ASYNC16(sb + Q_WSL + d, g1 + idx);
            CP_ASYNC16(sb + Q_WNH + d, g2 + idx);
            CP_ASYNC16(sb + Q_WNL + d, g3 + idx);
        }
        CP_COMMIT();
    }

    const int tl = lane >> 3, trow = lane & 7;
    uint32_t aoff[2], boff[4];
#pragma unroll
    for (int mi = 0; mi < 2; mi++) {
        int row = warp_m * 32 + mi * 16 + trow + (tl & 1) * 8;
        int col = (tl >> 1) * 8;
        aoff[mi] = (uint32_t)(row * SA + col) * 2;
    }
#pragma unroll
    for (int nh = 0; nh < 4; nh++) {
        int n = warp_n * 64 + nh * 16 + (tl >> 1) * 8 + trow;
        int col = (tl & 1) * 8;
        boff[nh] = (uint32_t)(n * SA + col) * 2;
    }

    int t = blockIdx.x;
    if (t >= ntiles) return;
    const int stride = gridDim.x;

    // prologue: convert (tile t, pass 0 = A0) into buffer 0
    {
        int tbase = t * 64;
#pragma unroll
        for (int it = 0; it < 16; it++) {
            int e = it * 128 + tid;              // 0..2047
            int row = e >> 5, c4 = e & 31;
            int grow = tbase + row;
            float4 v = make_float4(0.f, 0.f, 0.f, 0.f);
            if (grow < M)
                v = *reinterpret_cast<const float4*>(A0 + (size_t)grow * D + c4 * 4);
            uint2 hw, lw;
            split_f4(v, hw, lw);
            uint32_t d = (uint32_t)(row * SA + c4 * 4) * 2;
            *reinterpret_cast<uint2*>(smem + Q_A + d) = hw;
            *reinterpret_cast<uint2*>(smem + Q_A + 64 * SA * 2 + d) = lw;
        }
    }
    CP_WAIT0();

    float acc[2][8][4];
    int cur = 0;
    int pass = 0;
    while (t < ntiles) {
        __syncthreads();
        // next step: (t, pass) -> pass^1 same tile, or next tile pass 0
        int nt = pass ? t + stride : t;
        int np = pass ^ 1;
        bool hasnext = nt < ntiles;

        // prefetch next step's fp32 rows
        float4 st[16];
        if (hasnext) {
            const float* An = np ? A1 : A0;
            int nbase = nt * 64;
#pragma unroll
            for (int it = 0; it < 16; it++) {
                int e = it * 128 + tid;
                int row = e >> 5, c4 = e & 31;
                int grow = nbase + row;
                st[it] = make_float4(0.f, 0.f, 0.f, 0.f);
                if (grow < M)
                    st[it] = *reinterpret_cast<const float4*>(An + (size_t)grow * D + c4 * 4);
            }
        }

        if (pass == 0) {
#pragma unroll
            for (int i = 0; i < 2; i++)
#pragma unroll
                for (int j = 0; j < 8; j++)
#pragma unroll
                    for (int r = 0; r < 4; r++) acc[i][j][r] = 0.f;
        }

        // MMA from buffer cur with this pass's weights
        const uint32_t wh = sb + (pass ? Q_WNH : Q_WSH);
        const uint32_t wl = sb + (pass ? Q_WNL : Q_WSL);
        const uint32_t abase = sb + Q_A + cur * Q_ABUF;
        const uint32_t albase = abase + 64 * SA * 2;
#pragma unroll
        for (int ks = 0; ks < 8; ks++) {
            const uint32_t kb = ks * 32;
            uint32_t bh[16], bl[16];
#pragma unroll
            for (int nh = 0; nh < 4; nh++) {
                LDMATRIX_X4(bh[nh * 4], bh[nh * 4 + 1], bh[nh * 4 + 2], bh[nh * 4 + 3],
                            wh + boff[nh] + kb);
                LDMATRIX_X4(bl[nh * 4], bl[nh * 4 + 1], bl[nh * 4 + 2], bl[nh * 4 + 3],
                            wl + boff[nh] + kb);
            }
#pragma unroll
            for (int mi = 0; mi < 2; mi++) {
                uint32_t ah[4], al[4];
                LDMATRIX_X4(ah[0], ah[1], ah[2], ah[3], abase + aoff[mi] + kb);
                LDMATRIX_X4(al[0], al[1], al[2], al[3], albase + aoff[mi] + kb);
#pragma unroll
                for (int nj = 0; nj < 8; nj++) {
                    int bi = (nj >> 1) * 4 + (nj & 1) * 2;
                    MMA_BF16(acc[mi][nj], ah, bh[bi], bh[bi + 1]);
                    MMA_BF16(acc[mi][nj], al, bh[bi], bh[bi + 1]);
                    MMA_BF16(acc[mi][nj], ah, bl[bi], bl[bi + 1]);
                }
            }
        }

        // epilogue after pass 1
        if (pass == 1) {
            int tbase = t * 64;
            const int g = lane >> 2, t2 = lane & 3;
#pragma unroll
            for (int mi = 0; mi < 2; mi++) {
                int row0 = tbase + warp_m * 32 + mi * 16 + g;
                int row1 = row0 + 8;
#pragma unroll
                for (int nj = 0; nj < 8; nj++) {
                    int col = warp_n * 64 + nj * 8 + t2 * 2;
                    float bx = sbias[col], by = sbias[col + 1];
                    float2 v0 = make_float2(acc[mi][nj][0] + bx, acc[mi][nj][1] + by);
                    float2 v1 = make_float2(acc[mi][nj][2] + bx, acc[mi][nj][3] + by);
                    if (RELU) {
                        v0.x = fmaxf(v0.x, 0.f); v0.y = fmaxf(v0.y, 0.f);
                        v1.x = fmaxf(v1.x, 0.f); v1.y = fmaxf(v1.y, 0.f);
                    }
                    if (row0 < M)
                        *reinterpret_cast<float2*>(out + (size_t)row0 * D + col) = v0;
                    if (row1 < M)
                        *reinterpret_cast<float2*>(out + (size_t)row1 * D + col) = v1;
                }
            }
        }

        // convert prefetched step into the other buffer
        if (hasnext) {
            uint32_t dsth = Q_A + (cur ^ 1) * Q_ABUF;
            uint32_t dstl = dsth + 64 * SA * 2;
#pragma unroll
            for (int it = 0; it < 16; it++) {
                int e = it * 128 + tid;
                int row = e >> 5, c4 = e & 31;
                uint2 hw, lw;
                split_f4(st[it], hw, lw);
                uint32_t d = (uint32_t)(row * SA + c4 * 4) * 2;
                *reinterpret_cast<uint2*>(smem + dsth + d) = hw;
                *reinterpret_cast<uint2*>(smem + dstl + d) = lw;
            }
        }
        cur ^= 1;
        t = nt;
        pass = np;
    }
}

// ---------------- graph CSR build + mean aggregation ----------------
__global__ void hist_kernel(const int* __restrict__ dst, int* __restrict__ deg, int E) {
    int e = blockIdx.x * blockDim.x + threadIdx.x;
    if (e < E) atomicAdd(&deg[dst[e]], 1);
}

__global__ void scan_pass1(const int* __restrict__ deg, int* __restrict__ incl,
                           int* __restrict__ btot, int n) {
    __shared__ int wsum[32];
    int t = threadIdx.x;
    int i = blockIdx.x * 1024 + t;
    int v = (i < n) ? deg[i] : 0;
    int x = v;
#pragma unroll
    for (int o = 1; o < 32; o <<= 1) {
        int y = __shfl_up_sync(0xffffffffu, x, o);
        if ((t & 31) >= o) x += y;
    }
    if ((t & 31) == 31) wsum[t >> 5] = x;
    __syncthreads();
    if (t < 32) {
        int s = wsum[t];
#pragma unroll
        for (int o = 1; o < 32; o <<= 1) {
            int y = __shfl_up_sync(0xffffffffu, s, o);
            if (t >= o) s += y;
        }
        wsum[t] = s;
    }
    __syncthreads();
    int base = (t >= 32) ? wsum[(t >> 5) - 1] : 0;
    int inc = x + base;
    if (i < n) incl[i] = inc;
    if (t == 1023) btot[blockIdx.x] = inc;
}

__global__ void scan_pass2(int* __restrict__ btot, int nb) {
    __shared__ int s[64];
    int t = threadIdx.x;
    s[t] = (t < nb) ? btot[t] : 0;
    __syncthreads();
#pragma unroll
    for (int o = 1; o < 64; o <<= 1) {
        int v = (t >= o) ? s[t - o] : 0;
        __syncthreads();
        s[t] += v;
        __syncthreads();
    }
    if (t < nb) btot[t] = t ? s[t - 1] : 0;
}

__global__ void scan_pass3(const int* __restrict__ incl, const int* __restrict__ deg,
                           const int* __restrict__ btot, int* __restrict__ rp,
                           int* __restrict__ cur, int n) {
    int i = blockIdx.x * 1024 + threadIdx.x;
    if (i < n) {
        int r = btot[blockIdx.x] + incl[i] - deg[i];
        rp[i] = r;
        cur[i] = r;
    }
}

__global__ void fill_kernel(const int* __restrict__ src, const int* __restrict__ dst,
                            int* __restrict__ cur, int* __restrict__ es, int E) {
    int e = blockIdx.x * blockDim.x + threadIdx.x;
    if (e < E) {
        int p = atomicAdd(&cur[dst[e]], 1);
        es[p] = src[e];
    }
}

// one warp per dst node; 8-wide unrolled fp32 gather
__global__ void agg_kernel(const float* __restrict__ h, const int* __restrict__ rp,
                           const int* __restrict__ deg, const int* __restrict__ es,
                           float* __restrict__ hn, int ndst) {
    int lane = threadIdx.x & 31;
    int w = (blockIdx.x * blockDim.x + threadIdx.x) >> 5;
    if (w >= ndst) return;
    int start = rp[w];
    int cnt = deg[w];
    float4 a0 = make_float4(0.f, 0.f, 0.f, 0.f);
    float4 a1 = make_float4(0.f, 0.f, 0.f, 0.f);
    float4 a2 = make_float4(0.f, 0.f, 0.f, 0.f);
    float4 a3 = make_float4(0.f, 0.f, 0.f, 0.f);
    const float4* h4 = reinterpret_cast<const float4*>(h);
    for (int base = 0; base < cnt; base += 32) {
        int n = min(32, cnt - base);
        int sidx = (lane < n) ? es[start + base + lane] : 0;
        int j = 0;
        for (; j + 8 <= n; j += 8) {
            int s0 = __shfl_sync(0xffffffffu, sidx, j);
            int s1 = __shfl_sync(0xffffffffu, sidx, j + 1);
            int s2 = __shfl_sync(0xffffffffu, sidx, j + 2);
            int s3 = __shfl_sync(0xffffffffu, sidx, j + 3);
            int s4 = __shfl_sync(0xffffffffu, sidx, j + 4);
            int s5 = __shfl_sync(0xffffffffu, sidx, j + 5);
            int s6 = __shfl_sync(0xffffffffu, sidx, j + 6);
            int s7 = __shfl_sync(0xffffffffu, sidx, j + 7);
            float4 v0 = h4[(size_t)s0 * 32 + lane];
            float4 v1 = h4[(size_t)s1 * 32 + lane];
            float4 v2 = h4[(size_t)s2 * 32 + lane];
            float4 v3 = h4[(size_t)s3 * 32 + lane];
            float4 v4 = h4[(size_t)s4 * 32 + lane];
            float4 v5 = h4[(size_t)s5 * 32 + lane];
            float4 v6 = h4[(size_t)s6 * 32 + lane];
            float4 v7 = h4[(size_t)s7 * 32 + lane];
            a0.x += v0.x; a0.y += v0.y; a0.z += v0.z; a0.w += v0.w;
            a1.x += v1.x; a1.y += v1.y; a1.z += v1.z; a1.w += v1.w;
            a2.x += v2.x; a2.y += v2.y; a2.z += v2.z; a2.w += v2.w;
            a3.x += v3.x; a3.y += v3.y; a3.z += v3.z; a3.w += v3.w;
            a0.x += v4.x; a0.y += v4.y; a0.z += v4.z; a0.w += v4.w;
            a1.x += v5.x; a1.y += v5.y; a1.z += v5.z; a1.w += v5.w;
            a2.x += v6.x; a2.y += v6.y; a2.z += v6.z; a2.w += v6.w;
            a3.x += v7.x; a3.y += v7.y; a3.z += v7.z; a3.w += v7.w;
        }
        for (; j < n; j++) {
            int s0 = __shfl_sync(0xffffffffu, sidx, j);
            float4 v0 = h4[(size_t)s0 * 32 + lane];
            a0.x += v0.x; a0.y += v0.y; a0.z += v0.z; a0.w += v0.w;
        }
    }
    float inv = 1.0f / (float)max(cnt, 1);
    reinterpret_cast<float4*>(hn)[(size_t)w * 32 + lane] =
        make_float4((a0.x + a1.x + a2.x + a3.x) * inv, (a0.y + a1.y + a2.y + a3.y) * inv,
                    (a0.z + a1.z + a2.z + a3.z) * inv, (a0.w + a1.w + a2.w + a3.w) * inv);
}

// ---------------- launch ----------------
extern "C" void kernel_launch(void* const* d_in, const int* in_sizes, int n_in,
                              void* d_out, int out_size) {
    const float* feat    = (const float*)d_in[0];
    const int*   src0    = (const int*)d_in[1];
    const int*   dst0    = (const int*)d_in[2];
    const int*   src1    = (const int*)d_in[3];
    const int*   dst1    = (const int*)d_in[4];
    const float* W_init  = (const float*)d_in[5];
    const float* b_init  = (const float*)d_in[6];
    const float* W_self  = (const float*)d_in[7];
    const float* b_self  = (const float*)d_in[8];
    const float* W_neigh = (const float*)d_in[9];
    const float* b_neigh = (const float*)d_in[10];
    float* out = (float*)d_out;

    float *h0, *h1, *hn0, *hn1;
    __nv_bfloat16 *WiH, *WiL, *WsH, *WsL, *WnH, *WnL;
    int *deg0, *rp0, *cur0, *es0, *deg1, *rp1, *cur1, *es1, *incl, *btot;
    cudaGetSymbolAddress((void**)&h0,  g_h0);
    cudaGetSymbolAddress((void**)&h1,  g_h1);
    cudaGetSymbolAddress((void**)&hn0, g_hn0);
    cudaGetSymbolAddress((void**)&hn1, g_hn1);
    cudaGetSymbolAddress((void**)&WiH, g_WiH);
    cudaGetSymbolAddress((void**)&WiL, g_WiL);
    cudaGetSymbolAddress((void**)&WsH, g_WsH);
    cudaGetSymbolAddress((void**)&WsL, g_WsL);
    cudaGetSymbolAddress((void**)&WnH, g_WnH);
    cudaGetSymbolAddress((void**)&WnL, g_WnL);
    cudaGetSymbolAddress((void**)&deg0, g_deg0);
    cudaGetSymbolAddress((void**)&rp0,  g_rp0);
    cudaGetSymbolAddress((void**)&cur0, g_cur0);
    cudaGetSymbolAddress((void**)&es0,  g_es0);
    cudaGetSymbolAddress((void**)&deg1, g_deg1);
    cudaGetSymbolAddress((void**)&rp1,  g_rp1);
    cudaGetSymbolAddress((void**)&cur1, g_cur1);
    cudaGetSymbolAddress((void**)&es1,  g_es1);
    cudaGetSymbolAddress((void**)&incl, g_incl);
    cudaGetSymbolAddress((void**)&btot, g_btot);

    cudaFuncSetAttribute(gemm_persist,
                         cudaFuncAttributeMaxDynamicSharedMemorySize, P_SMEM);
    cudaFuncSetAttribute(gemm_persist_dual<true>,
                         cudaFuncAttributeMaxDynamicSharedMemorySize, Q_SMEM);
    cudaFuncSetAttribute(gemm_persist_dual<false>,
                         cudaFuncAttributeMaxDynamicSharedMemorySize, Q_SMEM);

    static cudaStream_t sA = nullptr;
    static cudaEvent_t evFork = nullptr, ev0 = nullptr, ev1 = nullptr;
    static int nsm = 0;
    if (!sA) {
        cudaStreamCreateWithFlags(&sA, cudaStreamNonBlocking);
        cudaEventCreateWithFlags(&evFork, cudaEventDisableTiming);
        cudaEventCreateWithFlags(&ev0, cudaEventDisableTiming);
        cudaEventCreateWithFlags(&ev1, cudaEventDisableTiming);
        cudaDeviceGetAttribute(&nsm, cudaDevAttrMultiProcessorCount, 0);
    }

    const int NB0 = (N_DST0 + 1023) / 1024;   // 49
    const int NB1 = (N_DST1 + 1023) / 1024;   // 10
    const int NT1 = (N_SRC0 + 127) / 128;     // 1563
    const int NT2 = (N_DST0 + 63) / 64;       // 782
    const int NT3 = (N_DST1 + 63) / 64;       // 157

    // ---- fork: CSR builds run on sA concurrent with wprep/gemm1 ----
    cudaEventRecord(evFork, 0);
    cudaStreamWaitEvent(sA, evFork, 0);

    cudaMemsetAsync(deg0, 0, N_DST0 * sizeof(int), sA);
    hist_kernel<<<(E0 + 255) / 256, 256, 0, sA>>>(dst0, deg0, E0);
    scan_pass1<<<NB0, 1024, 0, sA>>>(deg0, incl, btot, N_DST0);
    scan_pass2<<<1, 64, 0, sA>>>(btot, NB0);
    scan_pass3<<<NB0, 1024, 0, sA>>>(incl, deg0, btot, rp0, cur0, N_DST0);
    fill_kernel<<<(E0 + 255) / 256, 256, 0, sA>>>(src0, dst0, cur0, es0, E0);
    cudaEventRecord(ev0, sA);
    cudaMemsetAsync(deg1, 0, N_DST1 * sizeof(int), sA);
    hist_kernel<<<(E1 + 255) / 256, 256, 0, sA>>>(dst1, deg1, E1);
    scan_pass1<<<NB1, 1024, 0, sA>>>(deg1, incl, btot, N_DST1);
    scan_pass2<<<1, 64, 0, sA>>>(btot, NB1);
    scan_pass3<<<NB1, 1024, 0, sA>>>(incl, deg1, btot, rp1, cur1, N_DST1);
    fill_kernel<<<(E1 + 255) / 256, 256, 0, sA>>>(src1, dst1, cur1, es1, E1);
    cudaEventRecord(ev1, sA);

    // main: weight prep + persistent fc_init GEMM  h0 = relu(feat@Wi + bi)
    wprep_kernel<<<192, 256>>>(W_init, W_self, W_neigh, WiH, WiL, WsH, WsL, WnH, WnL);
    gemm_persist<<<nsm, 256, P_SMEM>>>(feat, WiH, WiL, b_init, h0, N_SRC0, NT1);

    // join CSR0, aggregate, persistent dual GEMM
    cudaStreamWaitEvent(0, ev0, 0);
    agg_kernel<<<N_DST0 / 8, 256>>>(h0, rp0, deg0, es0, hn0, N_DST0);
    gemm_persist_dual<true><<<nsm, 128, Q_SMEM>>>(
        h0, hn0, WsH, WsL, WnH, WnL, b_self, b_neigh, h1, N_DST0, NT2);

    // join CSR1, aggregate, persistent dual GEMM
    cudaStreamWaitEvent(0, ev1, 0);
    agg_kernel<<<N_DST1 / 8, 256>>>(h1, rp1, deg1, es1, hn1, N_DST1);
    gemm_persist_dual<false><<<nsm, 128, Q_SMEM>>>(
        h1, hn1, WsH, WsL, WnH, WnL, b_self, b_neigh, out, N_DST1, NT3);
}